// round 12
// baseline (speedup 1.0000x reference)
#include <cuda_runtime.h>
#include <cuda_bf16.h>
#include <cstdint>
#include <math.h>

#define CC 32
#define II 32
#define TT 40
#define RR 36
#define DD 1024
#define MM (CC*II*TT)     /* 40960 */
#define KK 2048
#define PITCH 40          /* bf16 elems per smem row (32 data + 8 pad) */

// ---------------- device scratch (no cudaMalloc allowed) ----------------
__device__ float g_wc[(size_t)MM*DD];                 // weightedContext fp32
__device__ float g_q1[(size_t)MM*DD];                 // updated query
__device__ __nv_bfloat16 g_cat[(size_t)MM*KK];        // [query | wc] bf16
__device__ __nv_bfloat16 g_WtL[(size_t)DD*KK];        // W_lin^T  [n][k]
__device__ __nv_bfloat16 g_WtG[(size_t)DD*KK];        // W_gate^T [n][k]

// ---------------- helpers ----------------
__device__ __forceinline__ uint32_t smem_u32(const void* p) {
    uint32_t a;
    asm("{ .reg .u64 t; cvta.to.shared.u64 t, %1; cvt.u32.u64 %0, t; }" : "=r"(a) : "l"(p));
    return a;
}
__device__ __forceinline__ void cpa16(uint32_t d, const void* s) {
    asm volatile("cp.async.cg.shared.global [%0], [%1], 16;" :: "r"(d), "l"(s));
}
__device__ __forceinline__ void cpa_commit() { asm volatile("cp.async.commit_group;" ::: "memory"); }
__device__ __forceinline__ void cpa_wait0()  { asm volatile("cp.async.wait_group 0;" ::: "memory"); }

#define MMA16816(d, a, b) \
  asm volatile("mma.sync.aligned.m16n8k16.row.col.f32.bf16.bf16.f32 " \
    "{%0,%1,%2,%3}, {%4,%5,%6,%7}, {%8,%9}, {%0,%1,%2,%3};" \
    : "+f"((d)[0]), "+f"((d)[1]), "+f"((d)[2]), "+f"((d)[3]) \
    : "r"((a)[0]), "r"((a)[1]), "r"((a)[2]), "r"((a)[3]), "r"((b)[0]), "r"((b)[1]))

// ---------------- prep: W^T -> bf16 ----------------
__global__ void prep_wt(const float* __restrict__ W, int which) {
    __shared__ float tile[32][33];
    __nv_bfloat16* Wt = which ? g_WtG : g_WtL;
    int n0 = blockIdx.x * 32;   // 32 tiles
    int k0 = blockIdx.y * 32;   // 64 tiles
    int tx = threadIdx.x, ty = threadIdx.y;  // (32, 8)
    #pragma unroll
    for (int j = 0; j < 4; j++)
        tile[ty + j*8][tx] = W[(size_t)(k0 + ty + j*8) * DD + n0 + tx];
    __syncthreads();
    #pragma unroll
    for (int j = 0; j < 4; j++)
        Wt[(size_t)(n0 + ty + j*8) * KK + k0 + tx] =
            __float2bfloat16(tile[tx][ty + j*8]);
}

// ---------------- prep: cat left half = broadcast caption (bf16) ----------------
__global__ void prep_catL(const float* __restrict__ cap) {
    size_t idx = (size_t)blockIdx.x * 256 + threadIdx.x;   // f4 index in [0, MM*256)
    int m  = (int)(idx >> 8);
    int dv = (int)(idx & 255);
    int c = m / (II*TT), t = m % TT;
    float4 v = reinterpret_cast<const float4*>(cap)[((size_t)(c*TT + t) << 8) + dv];
    __nv_bfloat162 lo = __floats2bfloat162_rn(v.x, v.y);
    __nv_bfloat162 hi = __floats2bfloat162_rn(v.z, v.w);
    __nv_bfloat162* dst = reinterpret_cast<__nv_bfloat162*>(g_cat + (size_t)m*KK + (size_t)dv*4);
    dst[0] = lo; dst[1] = hi;
}

// ---------------- fused attention step ----------------
// attn = leaky(ctx @ q^T); l2norm over t; softmax_r(9*attn^T); wc = attn @ ctx
__global__ __launch_bounds__(256)
void attn_kernel(const float* __restrict__ img, const float* __restrict__ cap, int iter) {
    extern __shared__ float sm[];
    float4* img4 = reinterpret_cast<float4*>(sm);   // 36*256 float4
    float* attn  = sm + RR*DD;                      // [36][40]  (r-major)
    float* attn2 = attn + RR*TT;                    // [40][36]  (t-major, softmaxed)
    int tid = threadIdx.x, lane = tid & 31, w = tid >> 5;
    int pair = blockIdx.x, c = pair >> 5, i = pair & 31;

    // load image region tile into smem
    const float4* imgv = reinterpret_cast<const float4*>(img) + (size_t)i * RR * 256;
    #pragma unroll
    for (int j = 0; j < 36; j++)
        img4[j*256 + tid] = imgv[j*256 + tid];
    __syncthreads();

    // phase B: dot products, Q rows in registers (2 t-rows per pass)
    const float4* qv = iter ? reinterpret_cast<const float4*>(g_q1)
                            : reinterpret_cast<const float4*>(cap);
    for (int base = 0; base < 48; base += 16) {
        int tA = base + w;
        int tB = base + 8 + w;
        bool hasB = (base < 32);
        int rA = iter ? (pair*TT + tA) : (c*TT + tA);
        size_t qa = (size_t)rA * 256;
        float4 Qa[8], Qb[8];
        #pragma unroll
        for (int j = 0; j < 8; j++) Qa[j] = qv[qa + j*32 + lane];
        if (hasB) {
            int rB = iter ? (pair*TT + tB) : (c*TT + tB);
            size_t qb = (size_t)rB * 256;
            #pragma unroll
            for (int j = 0; j < 8; j++) Qb[j] = qv[qb + j*32 + lane];
        }
        for (int r = 0; r < RR; r++) {
            float pa = 0.f, pb = 0.f;
            #pragma unroll
            for (int j = 0; j < 8; j++) {
                float4 v = img4[r*256 + j*32 + lane];
                pa += v.x*Qa[j].x + v.y*Qa[j].y + v.z*Qa[j].z + v.w*Qa[j].w;
                if (hasB) pb += v.x*Qb[j].x + v.y*Qb[j].y + v.z*Qb[j].z + v.w*Qb[j].w;
            }
            #pragma unroll
            for (int o = 16; o; o >>= 1) {
                pa += __shfl_xor_sync(0xffffffffu, pa, o);
                pb += __shfl_xor_sync(0xffffffffu, pb, o);
            }
            if (lane == 0) {
                attn[r*TT + tA] = pa;
                if (hasB) attn[r*TT + tB] = pb;
            }
        }
    }
    __syncthreads();

    // phase C: leaky relu + l2norm over t (per r)
    if (tid < RR) {
        float s = 0.f;
        #pragma unroll 8
        for (int t = 0; t < TT; t++) {
            float v = attn[tid*TT + t];
            v = (v > 0.f) ? v : 0.1f * v;
            attn[tid*TT + t] = v;
            s += v * v;
        }
        float inv = 1.f / (sqrtf(s) + 1e-8f);
        #pragma unroll 8
        for (int t = 0; t < TT; t++) attn[tid*TT + t] *= inv;
    }
    __syncthreads();

    // phase D: softmax over r (per t), temperature 9
    if (tid < TT) {
        float mx = -1e30f;
        for (int r = 0; r < RR; r++) mx = fmaxf(mx, attn[r*TT + tid]);
        float s = 0.f;
        for (int r = 0; r < RR; r++) {
            float e = expf(9.0f * (attn[r*TT + tid] - mx));
            attn2[tid*RR + r] = e;
            s += e;
        }
        float inv = 1.f / s;
        for (int r = 0; r < RR; r++) attn2[tid*RR + r] *= inv;
    }
    __syncthreads();

    // phase E: wc[t][d] = sum_r attn2[t][r] * img[r][d]; write fp32 + bf16(cat right)
    for (int tb = 0; tb < 5; tb++) {
        float4 acc[8];
        #pragma unroll
        for (int j = 0; j < 8; j++) acc[j] = make_float4(0.f, 0.f, 0.f, 0.f);
        for (int r = 0; r < RR; r++) {
            float4 v = img4[r*256 + tid];
            #pragma unroll
            for (int j = 0; j < 8; j++) {
                float a = attn2[(tb*8 + j)*RR + r];
                acc[j].x += v.x*a; acc[j].y += v.y*a;
                acc[j].z += v.z*a; acc[j].w += v.w*a;
            }
        }
        #pragma unroll
        for (int j = 0; j < 8; j++) {
            int t = tb*8 + j;
            size_t m = (size_t)pair*TT + t;
            reinterpret_cast<float4*>(g_wc)[m*256 + tid] = acc[j];
            __nv_bfloat162 lo = __floats2bfloat162_rn(acc[j].x, acc[j].y);
            __nv_bfloat162 hi = __floats2bfloat162_rn(acc[j].z, acc[j].w);
            __nv_bfloat162* dst = reinterpret_cast<__nv_bfloat162*>(
                g_cat + m*KK + DD + (size_t)tid*4);
            dst[0] = lo; dst[1] = hi;
        }
    }
}

// ---------------- similarity: score[i][c] += mean_t cos(cap, wc) ----------------
__global__ __launch_bounds__(256)
void sim_kernel(const float* __restrict__ cap, float* __restrict__ out, int addmode) {
    __shared__ float sbuf[TT];
    int tid = threadIdx.x, lane = tid & 31, w = tid >> 5;
    int pair = blockIdx.x, c = pair >> 5, i = pair & 31;
    const float4* capv = reinterpret_cast<const float4*>(cap);
    const float4* wcv  = reinterpret_cast<const float4*>(g_wc);
    for (int jt = 0; jt < 5; jt++) {
        int t = w + jt*8;
        size_t ca = ((size_t)(c*TT + t)) * 256;
        size_t wa = ((size_t)(pair*TT + t)) * 256;
        float dot = 0.f, na = 0.f, nb = 0.f;
        #pragma unroll
        for (int j = 0; j < 8; j++) {
            float4 a = capv[ca + j*32 + lane];
            float4 b = wcv[wa + j*32 + lane];
            dot += a.x*b.x + a.y*b.y + a.z*b.z + a.w*b.w;
            na  += a.x*a.x + a.y*a.y + a.z*a.z + a.w*a.w;
            nb  += b.x*b.x + b.y*b.y + b.z*b.z + b.w*b.w;
        }
        #pragma unroll
        for (int o = 16; o; o >>= 1) {
            dot += __shfl_xor_sync(0xffffffffu, dot, o);
            na  += __shfl_xor_sync(0xffffffffu, na, o);
            nb  += __shfl_xor_sync(0xffffffffu, nb, o);
        }
        if (lane == 0)
            sbuf[t] = dot / fmaxf(sqrtf(na) * sqrtf(nb), 1e-8f);
    }
    __syncthreads();
    if (tid == 0) {
        float s = 0.f;
        for (int t = 0; t < TT; t++) s += sbuf[t];
        s *= (1.0f / TT);
        size_t o = (size_t)i * CC + c;
        out[o] = addmode ? (out[o] + s) : s;
    }
}

// ---------------- gated-memory GEMM: q1 = cap*sig(g) + tanh(u)*(1-sig(g)) ----------------
// u = cat @ W_lin + b_lin ; g = cat @ W_gate + b_gate. Tile 128M x 64N, dual weights.
__global__ __launch_bounds__(256)
void gemm_gated(const float* __restrict__ bl, const float* __restrict__ bg,
                const float* __restrict__ cap) {
    __shared__ __align__(16) __nv_bfloat16 As[2][128*PITCH];
    __shared__ __align__(16) __nv_bfloat16 Bs[2][2][64*PITCH];
    int tid = threadIdx.x, lane = tid & 31, wid = tid >> 5;
    int warp_m = wid & 3, warp_n = wid >> 2;       // 4 x 2 warp grid
    int gq = lane >> 2, tg = lane & 3;
    int ntile = blockIdx.x, mtile = blockIdx.y;

    float aL[2][4][4], aG[2][4][4];
    #pragma unroll
    for (int mf = 0; mf < 2; mf++)
        #pragma unroll
        for (int nf = 0; nf < 4; nf++)
            #pragma unroll
            for (int q = 0; q < 4; q++) { aL[mf][nf][q] = 0.f; aG[mf][nf][q] = 0.f; }

    // load-index precompute
    int a_r0 = tid >> 2,        a_c0 = tid & 3;
    int a_r1 = (tid + 256) >> 2, a_c1 = tid & 3;   // rows 64..127
    int b_r  = tid >> 2,        b_c  = tid & 3;
    const __nv_bfloat16* Asrc0 = g_cat + ((size_t)(mtile*128 + a_r0))*KK + a_c0*8;
    const __nv_bfloat16* Asrc1 = g_cat + ((size_t)(mtile*128 + a_r1))*KK + a_c1*8;
    const __nv_bfloat16* BsrcL = g_WtL + ((size_t)(ntile*64 + b_r))*KK + b_c*8;
    const __nv_bfloat16* BsrcG = g_WtG + ((size_t)(ntile*64 + b_r))*KK + b_c*8;
    uint32_t Adst0[2], Adst1[2], BdstL[2], BdstG[2];
    #pragma unroll
    for (int b = 0; b < 2; b++) {
        Adst0[b] = smem_u32(&As[b][a_r0*PITCH + a_c0*8]);
        Adst1[b] = smem_u32(&As[b][a_r1*PITCH + a_c1*8]);
        BdstL[b] = smem_u32(&Bs[b][0][b_r*PITCH + b_c*8]);
        BdstG[b] = smem_u32(&Bs[b][1][b_r*PITCH + b_c*8]);
    }

    // prefetch stage 0
    cpa16(Adst0[0], Asrc0); cpa16(Adst1[0], Asrc1);
    cpa16(BdstL[0], BsrcL); cpa16(BdstG[0], BsrcG);
    cpa_commit();

    for (int s = 0; s < 64; s++) {
        cpa_wait0();
        __syncthreads();
        if (s + 1 < 64) {
            int nb = (s + 1) & 1;
            int k0 = (s + 1) * 32;
            cpa16(Adst0[nb], Asrc0 + k0); cpa16(Adst1[nb], Asrc1 + k0);
            cpa16(BdstL[nb], BsrcL + k0); cpa16(BdstG[nb], BsrcG + k0);
            cpa_commit();
        }
        int buf = s & 1;
        const uint32_t* A32 = reinterpret_cast<const uint32_t*>(&As[buf][0]);
        const uint32_t* BL  = reinterpret_cast<const uint32_t*>(&Bs[buf][0][0]);
        const uint32_t* BG  = reinterpret_cast<const uint32_t*>(&Bs[buf][1][0]);
        #pragma unroll
        for (int kk = 0; kk < 2; kk++) {
            int kw = kk * 8;   // uint32 offset for k = kk*16
            uint32_t afr[2][4];
            #pragma unroll
            for (int mf = 0; mf < 2; mf++) {
                int mo = warp_m*32 + mf*16;
                afr[mf][0] = A32[(mo + gq)     * 20 + kw + tg];
                afr[mf][1] = A32[(mo + gq + 8) * 20 + kw + tg];
                afr[mf][2] = A32[(mo + gq)     * 20 + kw + tg + 4];
                afr[mf][3] = A32[(mo + gq + 8) * 20 + kw + tg + 4];
            }
            uint32_t bfL[4][2], bfG[4][2];
            #pragma unroll
            for (int nf = 0; nf < 4; nf++) {
                int no = warp_n*32 + nf*8;
                bfL[nf][0] = BL[(no + gq) * 20 + kw + tg];
                bfL[nf][1] = BL[(no + gq) * 20 + kw + tg + 4];
                bfG[nf][0] = BG[(no + gq) * 20 + kw + tg];
                bfG[nf][1] = BG[(no + gq) * 20 + kw + tg + 4];
            }
            #pragma unroll
            for (int mf = 0; mf < 2; mf++)
                #pragma unroll
                for (int nf = 0; nf < 4; nf++) {
                    MMA16816(aL[mf][nf], afr[mf], bfL[nf]);
                    MMA16816(aG[mf][nf], afr[mf], bfG[nf]);
                }
        }
    }

    // fused epilogue
    #pragma unroll
    for (int mf = 0; mf < 2; mf++) {
        #pragma unroll
        for (int nf = 0; nf < 4; nf++) {
            int rb = mtile*128 + warp_m*32 + mf*16 + gq;
            int cb = ntile*64 + warp_n*32 + nf*8 + tg*2;
            float2 bl2 = *reinterpret_cast<const float2*>(bl + cb);
            float2 bg2 = *reinterpret_cast<const float2*>(bg + cb);
            #pragma unroll
            for (int h = 0; h < 2; h++) {
                int r = rb + h*8;
                int cc = r / (II*TT), t = r % TT;
                float2 cp = *reinterpret_cast<const float2*>(
                    cap + (((size_t)(cc*TT + t)) << 10) + cb);
                float u0 = tanhf(aL[mf][nf][h*2 + 0] + bl2.x);
                float u1 = tanhf(aL[mf][nf][h*2 + 1] + bl2.y);
                float s0 = 1.f / (1.f + expf(-(aG[mf][nf][h*2 + 0] + bg2.x)));
                float s1 = 1.f / (1.f + expf(-(aG[mf][nf][h*2 + 1] + bg2.y)));
                float2 o;
                o.x = cp.x * s0 + u0 * (1.f - s0);
                o.y = cp.y * s1 + u1 * (1.f - s1);
                *reinterpret_cast<float2*>(g_q1 + (size_t)r * DD + cb) = o;
            }
        }
    }
}

// ---------------- launch ----------------
extern "C" void kernel_launch(void* const* d_in, const int* in_sizes, int n_in,
                              void* d_out, int out_size) {
    (void)in_sizes; (void)n_in; (void)out_size;
    const float* img    = (const float*)d_in[0];
    const float* cap    = (const float*)d_in[1];
    const float* W_lin  = (const float*)d_in[2];
    const float* b_lin  = (const float*)d_in[3];
    const float* W_gate = (const float*)d_in[4];
    const float* b_gate = (const float*)d_in[5];
    float* out = (float*)d_out;

    const int SMEM_ATTN = (RR*DD + RR*TT + TT*RR) * (int)sizeof(float);  // 158976
    cudaFuncSetAttribute(attn_kernel, cudaFuncAttributeMaxDynamicSharedMemorySize, SMEM_ATTN);

    prep_wt<<<dim3(32, 64), dim3(32, 8)>>>(W_lin, 0);
    prep_wt<<<dim3(32, 64), dim3(32, 8)>>>(W_gate, 1);
    prep_catL<<<MM, 256>>>(cap);

    // iteration 0
    attn_kernel<<<CC*II, 256, SMEM_ATTN>>>(img, cap, 0);
    sim_kernel<<<CC*II, 256>>>(cap, out, 0);

    // gated memory (only live once: iteration 1's update is dead code)
    gemm_gated<<<dim3(16, 320), 256>>>(b_lin, b_gate, cap);

    // iteration 1
    attn_kernel<<<CC*II, 256, SMEM_ATTN>>>(img, cap, 1);
    sim_kernel<<<CC*II, 256>>>(cap, out, 1);
}

// round 13
// speedup vs baseline: 1.0006x; 1.0006x over previous
#include <cuda_runtime.h>
#include <cuda_bf16.h>
#include <cstdint>
#include <math.h>

#define CC 32
#define II 32
#define TT 40
#define RR 36
#define DD 1024
#define MM (CC*II*TT)     /* 40960 */
#define KK 2048
#define PITCH 40          /* bf16 elems per smem row (32 data + 8 pad) */

// ---------------- device scratch (no cudaMalloc allowed) ----------------
__device__ float g_wc[(size_t)MM*DD];                 // weightedContext fp32
__device__ float g_q1[(size_t)MM*DD];                 // updated query
__device__ __nv_bfloat16 g_cat[(size_t)MM*KK];        // [query | wc] bf16
__device__ __nv_bfloat16 g_WtL[(size_t)DD*KK];        // W_lin^T  [n][k]
__device__ __nv_bfloat16 g_WtG[(size_t)DD*KK];        // W_gate^T [n][k]

// ---------------- helpers ----------------
__device__ __forceinline__ uint32_t smem_u32(const void* p) {
    uint32_t a;
    asm("{ .reg .u64 t; cvta.to.shared.u64 t, %1; cvt.u32.u64 %0, t; }" : "=r"(a) : "l"(p));
    return a;
}
__device__ __forceinline__ void cpa16(uint32_t d, const void* s) {
    asm volatile("cp.async.cg.shared.global [%0], [%1], 16;" :: "r"(d), "l"(s));
}
__device__ __forceinline__ void cpa_commit() { asm volatile("cp.async.commit_group;" ::: "memory"); }
__device__ __forceinline__ void cpa_wait0()  { asm volatile("cp.async.wait_group 0;" ::: "memory"); }

#define MMA16816(d, a, b) \
  asm volatile("mma.sync.aligned.m16n8k16.row.col.f32.bf16.bf16.f32 " \
    "{%0,%1,%2,%3}, {%4,%5,%6,%7}, {%8,%9}, {%0,%1,%2,%3};" \
    : "+f"((d)[0]), "+f"((d)[1]), "+f"((d)[2]), "+f"((d)[3]) \
    : "r"((a)[0]), "r"((a)[1]), "r"((a)[2]), "r"((a)[3]), "r"((b)[0]), "r"((b)[1]))

// ---------------- prep: W^T -> bf16 ----------------
__global__ void prep_wt(const float* __restrict__ W, int which) {
    __shared__ float tile[32][33];
    __nv_bfloat16* Wt = which ? g_WtG : g_WtL;
    int n0 = blockIdx.x * 32;   // 32 tiles
    int k0 = blockIdx.y * 32;   // 64 tiles
    int tx = threadIdx.x, ty = threadIdx.y;  // (32, 8)
    #pragma unroll
    for (int j = 0; j < 4; j++)
        tile[ty + j*8][tx] = W[(size_t)(k0 + ty + j*8) * DD + n0 + tx];
    __syncthreads();
    #pragma unroll
    for (int j = 0; j < 4; j++)
        Wt[(size_t)(n0 + ty + j*8) * KK + k0 + tx] =
            __float2bfloat16(tile[tx][ty + j*8]);
}

// ---------------- prep: cat left half = broadcast caption (bf16) ----------------
__global__ void prep_catL(const float* __restrict__ cap) {
    size_t idx = (size_t)blockIdx.x * 256 + threadIdx.x;   // f4 index in [0, MM*256)
    int m  = (int)(idx >> 8);
    int dv = (int)(idx & 255);
    int c = m / (II*TT), t = m % TT;
    float4 v = reinterpret_cast<const float4*>(cap)[((size_t)(c*TT + t) << 8) + dv];
    __nv_bfloat162 lo = __floats2bfloat162_rn(v.x, v.y);
    __nv_bfloat162 hi = __floats2bfloat162_rn(v.z, v.w);
    __nv_bfloat162* dst = reinterpret_cast<__nv_bfloat162*>(g_cat + (size_t)m*KK + (size_t)dv*4);
    dst[0] = lo; dst[1] = hi;
}

// ---------------- fused attention step ----------------
// attn = leaky(ctx @ q^T); l2norm over t; softmax_r(9*attn^T); wc = attn @ ctx
__global__ __launch_bounds__(256)
void attn_kernel(const float* __restrict__ img, const float* __restrict__ cap, int iter) {
    extern __shared__ float sm[];
    float4* img4 = reinterpret_cast<float4*>(sm);   // 36*256 float4
    float* attn  = sm + RR*DD;                      // [36][40]  (r-major)
    float* attn2 = attn + RR*TT;                    // [40][36]  (t-major, softmaxed)
    int tid = threadIdx.x, lane = tid & 31, w = tid >> 5;
    int pair = blockIdx.x, c = pair >> 5, i = pair & 31;

    // load image region tile into smem
    const float4* imgv = reinterpret_cast<const float4*>(img) + (size_t)i * RR * 256;
    #pragma unroll
    for (int j = 0; j < 36; j++)
        img4[j*256 + tid] = imgv[j*256 + tid];
    __syncthreads();

    // phase B: dot products, Q rows in registers (2 t-rows per pass)
    const float4* qv = iter ? reinterpret_cast<const float4*>(g_q1)
                            : reinterpret_cast<const float4*>(cap);
    for (int base = 0; base < 48; base += 16) {
        int tA = base + w;
        int tB = base + 8 + w;
        bool hasB = (base < 32);
        int rA = iter ? (pair*TT + tA) : (c*TT + tA);
        size_t qa = (size_t)rA * 256;
        float4 Qa[8], Qb[8];
        #pragma unroll
        for (int j = 0; j < 8; j++) Qa[j] = qv[qa + j*32 + lane];
        if (hasB) {
            int rB = iter ? (pair*TT + tB) : (c*TT + tB);
            size_t qb = (size_t)rB * 256;
            #pragma unroll
            for (int j = 0; j < 8; j++) Qb[j] = qv[qb + j*32 + lane];
        }
        for (int r = 0; r < RR; r++) {
            float pa = 0.f, pb = 0.f;
            #pragma unroll
            for (int j = 0; j < 8; j++) {
                float4 v = img4[r*256 + j*32 + lane];
                pa += v.x*Qa[j].x + v.y*Qa[j].y + v.z*Qa[j].z + v.w*Qa[j].w;
                if (hasB) pb += v.x*Qb[j].x + v.y*Qb[j].y + v.z*Qb[j].z + v.w*Qb[j].w;
            }
            #pragma unroll
            for (int o = 16; o; o >>= 1) {
                pa += __shfl_xor_sync(0xffffffffu, pa, o);
                pb += __shfl_xor_sync(0xffffffffu, pb, o);
            }
            if (lane == 0) {
                attn[r*TT + tA] = pa;
                if (hasB) attn[r*TT + tB] = pb;
            }
        }
    }
    __syncthreads();

    // phase C: leaky relu + l2norm over t (per r)
    if (tid < RR) {
        float s = 0.f;
        #pragma unroll 8
        for (int t = 0; t < TT; t++) {
            float v = attn[tid*TT + t];
            v = (v > 0.f) ? v : 0.1f * v;
            attn[tid*TT + t] = v;
            s += v * v;
        }
        float inv = 1.f / (sqrtf(s) + 1e-8f);
        #pragma unroll 8
        for (int t = 0; t < TT; t++) attn[tid*TT + t] *= inv;
    }
    __syncthreads();

    // phase D: softmax over r (per t), temperature 9
    if (tid < TT) {
        float mx = -1e30f;
        for (int r = 0; r < RR; r++) mx = fmaxf(mx, attn[r*TT + tid]);
        float s = 0.f;
        for (int r = 0; r < RR; r++) {
            float e = expf(9.0f * (attn[r*TT + tid] - mx));
            attn2[tid*RR + r] = e;
            s += e;
        }
        float inv = 1.f / s;
        for (int r = 0; r < RR; r++) attn2[tid*RR + r] *= inv;
    }
    __syncthreads();

    // phase E: wc[t][d] = sum_r attn2[t][r] * img[r][d]; write fp32 + bf16(cat right)
    for (int tb = 0; tb < 5; tb++) {
        float4 acc[8];
        #pragma unroll
        for (int j = 0; j < 8; j++) acc[j] = make_float4(0.f, 0.f, 0.f, 0.f);
        for (int r = 0; r < RR; r++) {
            float4 v = img4[r*256 + tid];
            #pragma unroll
            for (int j = 0; j < 8; j++) {
                float a = attn2[(tb*8 + j)*RR + r];
                acc[j].x += v.x*a; acc[j].y += v.y*a;
                acc[j].z += v.z*a; acc[j].w += v.w*a;
            }
        }
        #pragma unroll
        for (int j = 0; j < 8; j++) {
            int t = tb*8 + j;
            size_t m = (size_t)pair*TT + t;
            reinterpret_cast<float4*>(g_wc)[m*256 + tid] = acc[j];
            __nv_bfloat162 lo = __floats2bfloat162_rn(acc[j].x, acc[j].y);
            __nv_bfloat162 hi = __floats2bfloat162_rn(acc[j].z, acc[j].w);
            __nv_bfloat162* dst = reinterpret_cast<__nv_bfloat162*>(
                g_cat + m*KK + DD + (size_t)tid*4);
            dst[0] = lo; dst[1] = hi;
        }
    }
}

// ---------------- similarity: score[i][c] += mean_t cos(cap, wc) ----------------
__global__ __launch_bounds__(256)
void sim_kernel(const float* __restrict__ cap, float* __restrict__ out, int addmode) {
    __shared__ float sbuf[TT];
    int tid = threadIdx.x, lane = tid & 31, w = tid >> 5;
    int pair = blockIdx.x, c = pair >> 5, i = pair & 31;
    const float4* capv = reinterpret_cast<const float4*>(cap);
    const float4* wcv  = reinterpret_cast<const float4*>(g_wc);
    for (int jt = 0; jt < 5; jt++) {
        int t = w + jt*8;
        size_t ca = ((size_t)(c*TT + t)) * 256;
        size_t wa = ((size_t)(pair*TT + t)) * 256;
        float dot = 0.f, na = 0.f, nb = 0.f;
        #pragma unroll
        for (int j = 0; j < 8; j++) {
            float4 a = capv[ca + j*32 + lane];
            float4 b = wcv[wa + j*32 + lane];
            dot += a.x*b.x + a.y*b.y + a.z*b.z + a.w*b.w;
            na  += a.x*a.x + a.y*a.y + a.z*a.z + a.w*a.w;
            nb  += b.x*b.x + b.y*b.y + b.z*b.z + b.w*b.w;
        }
        #pragma unroll
        for (int o = 16; o; o >>= 1) {
            dot += __shfl_xor_sync(0xffffffffu, dot, o);
            na  += __shfl_xor_sync(0xffffffffu, na, o);
            nb  += __shfl_xor_sync(0xffffffffu, nb, o);
        }
        if (lane == 0)
            sbuf[t] = dot / fmaxf(sqrtf(na) * sqrtf(nb), 1e-8f);
    }
    __syncthreads();
    if (tid == 0) {
        float s = 0.f;
        for (int t = 0; t < TT; t++) s += sbuf[t];
        s *= (1.0f / TT);
        size_t o = (size_t)i * CC + c;
        out[o] = addmode ? (out[o] + s) : s;
    }
}

// ---------------- gated-memory GEMM: q1 = cap*sig(g) + tanh(u)*(1-sig(g)) ----------------
// u = cat @ W_lin + b_lin ; g = cat @ W_gate + b_gate. Tile 128M x 64N, dual weights.
__global__ __launch_bounds__(256)
void gemm_gated(const float* __restrict__ bl, const float* __restrict__ bg,
                const float* __restrict__ cap) {
    __shared__ __align__(16) __nv_bfloat16 As[2][128*PITCH];
    __shared__ __align__(16) __nv_bfloat16 Bs[2][2][64*PITCH];
    int tid = threadIdx.x, lane = tid & 31, wid = tid >> 5;
    int warp_m = wid & 3, warp_n = wid >> 2;       // 4 x 2 warp grid
    int gq = lane >> 2, tg = lane & 3;
    int ntile = blockIdx.x, mtile = blockIdx.y;

    float aL[2][4][4], aG[2][4][4];
    #pragma unroll
    for (int mf = 0; mf < 2; mf++)
        #pragma unroll
        for (int nf = 0; nf < 4; nf++)
            #pragma unroll
            for (int q = 0; q < 4; q++) { aL[mf][nf][q] = 0.f; aG[mf][nf][q] = 0.f; }

    // load-index precompute
    int a_r0 = tid >> 2,        a_c0 = tid & 3;
    int a_r1 = (tid + 256) >> 2, a_c1 = tid & 3;   // rows 64..127
    int b_r  = tid >> 2,        b_c  = tid & 3;
    const __nv_bfloat16* Asrc0 = g_cat + ((size_t)(mtile*128 + a_r0))*KK + a_c0*8;
    const __nv_bfloat16* Asrc1 = g_cat + ((size_t)(mtile*128 + a_r1))*KK + a_c1*8;
    const __nv_bfloat16* BsrcL = g_WtL + ((size_t)(ntile*64 + b_r))*KK + b_c*8;
    const __nv_bfloat16* BsrcG = g_WtG + ((size_t)(ntile*64 + b_r))*KK + b_c*8;
    uint32_t Adst0[2], Adst1[2], BdstL[2], BdstG[2];
    #pragma unroll
    for (int b = 0; b < 2; b++) {
        Adst0[b] = smem_u32(&As[b][a_r0*PITCH + a_c0*8]);
        Adst1[b] = smem_u32(&As[b][a_r1*PITCH + a_c1*8]);
        BdstL[b] = smem_u32(&Bs[b][0][b_r*PITCH + b_c*8]);
        BdstG[b] = smem_u32(&Bs[b][1][b_r*PITCH + b_c*8]);
    }

    // prefetch stage 0
    cpa16(Adst0[0], Asrc0); cpa16(Adst1[0], Asrc1);
    cpa16(BdstL[0], BsrcL); cpa16(BdstG[0], BsrcG);
    cpa_commit();

    for (int s = 0; s < 64; s++) {
        cpa_wait0();
        __syncthreads();
        if (s + 1 < 64) {
            int nb = (s + 1) & 1;
            int k0 = (s + 1) * 32;
            cpa16(Adst0[nb], Asrc0 + k0); cpa16(Adst1[nb], Asrc1 + k0);
            cpa16(BdstL[nb], BsrcL + k0); cpa16(BdstG[nb], BsrcG + k0);
            cpa_commit();
        }
        int buf = s & 1;
        const uint32_t* A32 = reinterpret_cast<const uint32_t*>(&As[buf][0]);
        const uint32_t* BL  = reinterpret_cast<const uint32_t*>(&Bs[buf][0][0]);
        const uint32_t* BG  = reinterpret_cast<const uint32_t*>(&Bs[buf][1][0]);
        #pragma unroll
        for (int kk = 0; kk < 2; kk++) {
            int kw = kk * 8;   // uint32 offset for k = kk*16
            uint32_t afr[2][4];
            #pragma unroll
            for (int mf = 0; mf < 2; mf++) {
                int mo = warp_m*32 + mf*16;
                afr[mf][0] = A32[(mo + gq)     * 20 + kw + tg];
                afr[mf][1] = A32[(mo + gq + 8) * 20 + kw + tg];
                afr[mf][2] = A32[(mo + gq)     * 20 + kw + tg + 4];
                afr[mf][3] = A32[(mo + gq + 8) * 20 + kw + tg + 4];
            }
            uint32_t bfL[4][2], bfG[4][2];
            #pragma unroll
            for (int nf = 0; nf < 4; nf++) {
                int no = warp_n*32 + nf*8;
                bfL[nf][0] = BL[(no + gq) * 20 + kw + tg];
                bfL[nf][1] = BL[(no + gq) * 20 + kw + tg + 4];
                bfG[nf][0] = BG[(no + gq) * 20 + kw + tg];
                bfG[nf][1] = BG[(no + gq) * 20 + kw + tg + 4];
            }
            #pragma unroll
            for (int mf = 0; mf < 2; mf++)
                #pragma unroll
                for (int nf = 0; nf < 4; nf++) {
                    MMA16816(aL[mf][nf], afr[mf], bfL[nf]);
                    MMA16816(aG[mf][nf], afr[mf], bfG[nf]);
                }
        }
    }

    // fused epilogue
    #pragma unroll
    for (int mf = 0; mf < 2; mf++) {
        #pragma unroll
        for (int nf = 0; nf < 4; nf++) {
            int rb = mtile*128 + warp_m*32 + mf*16 + gq;
            int cb = ntile*64 + warp_n*32 + nf*8 + tg*2;
            float2 bl2 = *reinterpret_cast<const float2*>(bl + cb);
            float2 bg2 = *reinterpret_cast<const float2*>(bg + cb);
            #pragma unroll
            for (int h = 0; h < 2; h++) {
                int r = rb + h*8;
                int cc = r / (II*TT), t = r % TT;
                float2 cp = *reinterpret_cast<const float2*>(
                    cap + (((size_t)(cc*TT + t)) << 10) + cb);
                float u0 = tanhf(aL[mf][nf][h*2 + 0] + bl2.x);
                float u1 = tanhf(aL[mf][nf][h*2 + 1] + bl2.y);
                float s0 = 1.f / (1.f + expf(-(aG[mf][nf][h*2 + 0] + bg2.x)));
                float s1 = 1.f / (1.f + expf(-(aG[mf][nf][h*2 + 1] + bg2.y)));
                float2 o;
                o.x = cp.x * s0 + u0 * (1.f - s0);
                o.y = cp.y * s1 + u1 * (1.f - s1);
                *reinterpret_cast<float2*>(g_q1 + (size_t)r * DD + cb) = o;
            }
        }
    }
}

// ---------------- launch ----------------
extern "C" void kernel_launch(void* const* d_in, const int* in_sizes, int n_in,
                              void* d_out, int out_size) {
    (void)in_sizes; (void)n_in; (void)out_size;
    const float* img    = (const float*)d_in[0];
    const float* cap    = (const float*)d_in[1];
    const float* W_lin  = (const float*)d_in[2];
    const float* b_lin  = (const float*)d_in[3];
    const float* W_gate = (const float*)d_in[4];
    const float* b_gate = (const float*)d_in[5];
    float* out = (float*)d_out;

    const int SMEM_ATTN = (RR*DD + RR*TT + TT*RR) * (int)sizeof(float);  // 158976
    cudaFuncSetAttribute(attn_kernel, cudaFuncAttributeMaxDynamicSharedMemorySize, SMEM_ATTN);

    prep_wt<<<dim3(32, 64), dim3(32, 8)>>>(W_lin, 0);
    prep_wt<<<dim3(32, 64), dim3(32, 8)>>>(W_gate, 1);
    prep_catL<<<MM, 256>>>(cap);

    // iteration 0
    attn_kernel<<<CC*II, 256, SMEM_ATTN>>>(img, cap, 0);
    sim_kernel<<<CC*II, 256>>>(cap, out, 0);

    // gated memory (only live once: iteration 1's update is dead code)
    gemm_gated<<<dim3(16, 320), 256>>>(b_lin, b_gate, cap);

    // iteration 1
    attn_kernel<<<CC*II, 256, SMEM_ATTN>>>(img, cap, 1);
    sim_kernel<<<CC*II, 256>>>(cap, out, 1);
}

// round 14
// speedup vs baseline: 1.3822x; 1.3814x over previous
#include <cuda_runtime.h>
#include <cuda_bf16.h>
#include <cstdint>
#include <math.h>

#define CC 32
#define II 32
#define TT 40
#define RR 36
#define DD 1024
#define MM (CC*II*TT)     /* 40960 */
#define KK 2048
#define PITCH 40          /* bf16 elems per smem row (32 data + 8 pad) */

// ---------------- device scratch (no cudaMalloc allowed) ----------------
__device__ float g_wc[(size_t)MM*DD];                 // weightedContext fp32 (for sim)
__device__ __nv_bfloat16 g_wcb[(size_t)MM*DD];        // weightedContext bf16 (GEMM A)
__device__ float g_q1[(size_t)MM*DD];                 // updated query
__device__ __nv_bfloat16 g_capb[(size_t)CC*TT*DD];    // caption bf16
__device__ float g_capU[(size_t)CC*TT*DD];            // cap @ W_lin_top + b_lin
__device__ float g_capG[(size_t)CC*TT*DD];            // cap @ W_gate_top + b_gate
__device__ __nv_bfloat16 g_WtL[(size_t)DD*KK];        // W_lin^T  [n][k]
__device__ __nv_bfloat16 g_WtG[(size_t)DD*KK];        // W_gate^T [n][k]

// ---------------- helpers ----------------
__device__ __forceinline__ uint32_t smem_u32(const void* p) {
    uint32_t a;
    asm("{ .reg .u64 t; cvta.to.shared.u64 t, %1; cvt.u32.u64 %0, t; }" : "=r"(a) : "l"(p));
    return a;
}
__device__ __forceinline__ void cpa16(uint32_t d, const void* s) {
    asm volatile("cp.async.cg.shared.global [%0], [%1], 16;" :: "r"(d), "l"(s));
}
__device__ __forceinline__ void cpa_commit() { asm volatile("cp.async.commit_group;" ::: "memory"); }
__device__ __forceinline__ void cpa_wait0()  { asm volatile("cp.async.wait_group 0;" ::: "memory"); }

#define MMA16816(d, a, b) \
  asm volatile("mma.sync.aligned.m16n8k16.row.col.f32.bf16.bf16.f32 " \
    "{%0,%1,%2,%3}, {%4,%5,%6,%7}, {%8,%9}, {%0,%1,%2,%3};" \
    : "+f"((d)[0]), "+f"((d)[1]), "+f"((d)[2]), "+f"((d)[3]) \
    : "r"((a)[0]), "r"((a)[1]), "r"((a)[2]), "r"((a)[3]), "r"((b)[0]), "r"((b)[1]))

// ---------------- prep: W^T -> bf16 ----------------
__global__ void prep_wt(const float* __restrict__ W, int which) {
    __shared__ float tile[32][33];
    __nv_bfloat16* Wt = which ? g_WtG : g_WtL;
    int n0 = blockIdx.x * 32;
    int k0 = blockIdx.y * 32;
    int tx = threadIdx.x, ty = threadIdx.y;  // (32, 8)
    #pragma unroll
    for (int j = 0; j < 4; j++)
        tile[ty + j*8][tx] = W[(size_t)(k0 + ty + j*8) * DD + n0 + tx];
    __syncthreads();
    #pragma unroll
    for (int j = 0; j < 4; j++)
        Wt[(size_t)(n0 + ty + j*8) * KK + k0 + tx] =
            __float2bfloat16(tile[tx][ty + j*8]);
}

// ---------------- prep: caption fp32 -> bf16 ----------------
__global__ void prep_capb(const float* __restrict__ cap) {
    size_t idx = (size_t)blockIdx.x * 256 + threadIdx.x;   // float4 index
    float4 v = reinterpret_cast<const float4*>(cap)[idx];
    __nv_bfloat162 lo = __floats2bfloat162_rn(v.x, v.y);
    __nv_bfloat162 hi = __floats2bfloat162_rn(v.z, v.w);
    __nv_bfloat162* dst = reinterpret_cast<__nv_bfloat162*>(g_capb + idx*4);
    dst[0] = lo; dst[1] = hi;
}

// ---------------- fused attention step ----------------
__global__ __launch_bounds__(256)
void attn_kernel(const float* __restrict__ img, const float* __restrict__ cap, int iter) {
    extern __shared__ float sm[];
    float4* img4 = reinterpret_cast<float4*>(sm);   // 36*256 float4
    float* attn  = sm + RR*DD;                      // [36][40]  (r-major)
    float* attn2 = attn + RR*TT;                    // [40][36]  (t-major, softmaxed)
    int tid = threadIdx.x, lane = tid & 31, w = tid >> 5;
    int pair = blockIdx.x, c = pair >> 5, i = pair & 31;

    const float4* imgv = reinterpret_cast<const float4*>(img) + (size_t)i * RR * 256;
    #pragma unroll
    for (int j = 0; j < 36; j++)
        img4[j*256 + tid] = imgv[j*256 + tid];
    __syncthreads();

    const float4* qv = iter ? reinterpret_cast<const float4*>(g_q1)
                            : reinterpret_cast<const float4*>(cap);
    for (int base = 0; base < 48; base += 16) {
        int tA = base + w;
        int tB = base + 8 + w;
        bool hasB = (base < 32);
        int rA = iter ? (pair*TT + tA) : (c*TT + tA);
        size_t qa = (size_t)rA * 256;
        float4 Qa[8], Qb[8];
        #pragma unroll
        for (int j = 0; j < 8; j++) Qa[j] = qv[qa + j*32 + lane];
        if (hasB) {
            int rB = iter ? (pair*TT + tB) : (c*TT + tB);
            size_t qb = (size_t)rB * 256;
            #pragma unroll
            for (int j = 0; j < 8; j++) Qb[j] = qv[qb + j*32 + lane];
        }
        for (int r = 0; r < RR; r++) {
            float pa = 0.f, pb = 0.f;
            #pragma unroll
            for (int j = 0; j < 8; j++) {
                float4 v = img4[r*256 + j*32 + lane];
                pa += v.x*Qa[j].x + v.y*Qa[j].y + v.z*Qa[j].z + v.w*Qa[j].w;
                if (hasB) pb += v.x*Qb[j].x + v.y*Qb[j].y + v.z*Qb[j].z + v.w*Qb[j].w;
            }
            #pragma unroll
            for (int o = 16; o; o >>= 1) {
                pa += __shfl_xor_sync(0xffffffffu, pa, o);
                pb += __shfl_xor_sync(0xffffffffu, pb, o);
            }
            if (lane == 0) {
                attn[r*TT + tA] = pa;
                if (hasB) attn[r*TT + tB] = pb;
            }
        }
    }
    __syncthreads();

    // leaky relu + l2norm over t (per r)
    if (tid < RR) {
        float s = 0.f;
        #pragma unroll 8
        for (int t = 0; t < TT; t++) {
            float v = attn[tid*TT + t];
            v = (v > 0.f) ? v : 0.1f * v;
            attn[tid*TT + t] = v;
            s += v * v;
        }
        float inv = 1.f / (sqrtf(s) + 1e-8f);
        #pragma unroll 8
        for (int t = 0; t < TT; t++) attn[tid*TT + t] *= inv;
    }
    __syncthreads();

    // softmax over r (per t), temperature 9
    if (tid < TT) {
        float mx = -1e30f;
        for (int r = 0; r < RR; r++) mx = fmaxf(mx, attn[r*TT + tid]);
        float s = 0.f;
        for (int r = 0; r < RR; r++) {
            float e = expf(9.0f * (attn[r*TT + tid] - mx));
            attn2[tid*RR + r] = e;
            s += e;
        }
        float inv = 1.f / s;
        for (int r = 0; r < RR; r++) attn2[tid*RR + r] *= inv;
    }
    __syncthreads();

    // wc[t][d] = sum_r attn2[t][r] * img[r][d]; write fp32 (sim) + bf16 (GEMM A)
    for (int tb = 0; tb < 5; tb++) {
        float4 acc[8];
        #pragma unroll
        for (int j = 0; j < 8; j++) acc[j] = make_float4(0.f, 0.f, 0.f, 0.f);
        for (int r = 0; r < RR; r++) {
            float4 v = img4[r*256 + tid];
            #pragma unroll
            for (int j = 0; j < 8; j++) {
                float a = attn2[(tb*8 + j)*RR + r];
                acc[j].x += v.x*a; acc[j].y += v.y*a;
                acc[j].z += v.z*a; acc[j].w += v.w*a;
            }
        }
        #pragma unroll
        for (int j = 0; j < 8; j++) {
            int t = tb*8 + j;
            size_t m = (size_t)pair*TT + t;
            reinterpret_cast<float4*>(g_wc)[m*256 + tid] = acc[j];
            __nv_bfloat162 lo = __floats2bfloat162_rn(acc[j].x, acc[j].y);
            __nv_bfloat162 hi = __floats2bfloat162_rn(acc[j].z, acc[j].w);
            __nv_bfloat162* dst = reinterpret_cast<__nv_bfloat162*>(
                g_wcb + m*DD + (size_t)tid*4);
            dst[0] = lo; dst[1] = hi;
        }
    }
}

// ---------------- similarity ----------------
__global__ __launch_bounds__(256)
void sim_kernel(const float* __restrict__ cap, float* __restrict__ out, int addmode) {
    __shared__ float sbuf[TT];
    int tid = threadIdx.x, lane = tid & 31, w = tid >> 5;
    int pair = blockIdx.x, c = pair >> 5, i = pair & 31;
    const float4* capv = reinterpret_cast<const float4*>(cap);
    const float4* wcv  = reinterpret_cast<const float4*>(g_wc);
    for (int jt = 0; jt < 5; jt++) {
        int t = w + jt*8;
        size_t ca = ((size_t)(c*TT + t)) * 256;
        size_t wa = ((size_t)(pair*TT + t)) * 256;
        float dot = 0.f, na = 0.f, nb = 0.f;
        #pragma unroll
        for (int j = 0; j < 8; j++) {
            float4 a = capv[ca + j*32 + lane];
            float4 b = wcv[wa + j*32 + lane];
            dot += a.x*b.x + a.y*b.y + a.z*b.z + a.w*b.w;
            na  += a.x*a.x + a.y*a.y + a.z*a.z + a.w*a.w;
            nb  += b.x*b.x + b.y*b.y + b.z*b.z + b.w*b.w;
        }
        #pragma unroll
        for (int o = 16; o; o >>= 1) {
            dot += __shfl_xor_sync(0xffffffffu, dot, o);
            na  += __shfl_xor_sync(0xffffffffu, na, o);
            nb  += __shfl_xor_sync(0xffffffffu, nb, o);
        }
        if (lane == 0)
            sbuf[t] = dot / fmaxf(sqrtf(na) * sqrtf(nb), 1e-8f);
    }
    __syncthreads();
    if (tid == 0) {
        float s = 0.f;
        for (int t = 0; t < TT; t++) s += sbuf[t];
        s *= (1.0f / TT);
        size_t o = (size_t)i * CC + c;
        out[o] = addmode ? (out[o] + s) : s;
    }
}

// ---------------- dual-weight GEMM, K=1024 ----------------
// MODE 0: capU/capG = cap_bf16 @ Wt[:, 0:1024]^T + bias        (M=1280)
// MODE 1: u = wc @ Wt[:,1024:2048]^T + capU;  g = ... + capG;
//         q1 = cap*sig(g) + tanh(u)*(1-sig(g))                  (M=40960)
template<int MODE>
__global__ __launch_bounds__(256)
void gemm_dual(const float* __restrict__ bl, const float* __restrict__ bg,
               const float* __restrict__ cap) {
    __shared__ __align__(16) __nv_bfloat16 As[2][128*PITCH];
    __shared__ __align__(16) __nv_bfloat16 Bs[2][2][64*PITCH];
    int tid = threadIdx.x, lane = tid & 31, wid = tid >> 5;
    int warp_m = wid & 3, warp_n = wid >> 2;       // 4 x 2 warp grid
    int gq = lane >> 2, tg = lane & 3;
    int ntile = blockIdx.x, mtile = blockIdx.y;

    const __nv_bfloat16* Abase = MODE ? g_wcb : g_capb;
    const int koff = MODE ? DD : 0;

    float aL[2][4][4], aG[2][4][4];
    #pragma unroll
    for (int mf = 0; mf < 2; mf++)
        #pragma unroll
        for (int nf = 0; nf < 4; nf++)
            #pragma unroll
            for (int q = 0; q < 4; q++) { aL[mf][nf][q] = 0.f; aG[mf][nf][q] = 0.f; }

    int a_r0 = tid >> 2,         a_c0 = tid & 3;
    int a_r1 = (tid + 256) >> 2, a_c1 = tid & 3;
    int b_r  = tid >> 2,         b_c  = tid & 3;
    const __nv_bfloat16* Asrc0 = Abase + ((size_t)(mtile*128 + a_r0))*DD + a_c0*8;
    const __nv_bfloat16* Asrc1 = Abase + ((size_t)(mtile*128 + a_r1))*DD + a_c1*8;
    const __nv_bfloat16* BsrcL = g_WtL + ((size_t)(ntile*64 + b_r))*KK + koff + b_c*8;
    const __nv_bfloat16* BsrcG = g_WtG + ((size_t)(ntile*64 + b_r))*KK + koff + b_c*8;
    uint32_t Adst0[2], Adst1[2], BdstL[2], BdstG[2];
    #pragma unroll
    for (int b = 0; b < 2; b++) {
        Adst0[b] = smem_u32(&As[b][a_r0*PITCH + a_c0*8]);
        Adst1[b] = smem_u32(&As[b][a_r1*PITCH + a_c1*8]);
        BdstL[b] = smem_u32(&Bs[b][0][b_r*PITCH + b_c*8]);
        BdstG[b] = smem_u32(&Bs[b][1][b_r*PITCH + b_c*8]);
    }

    cpa16(Adst0[0], Asrc0); cpa16(Adst1[0], Asrc1);
    cpa16(BdstL[0], BsrcL); cpa16(BdstG[0], BsrcG);
    cpa_commit();

    const int NSTEP = 32;   // K = 1024
    for (int s = 0; s < NSTEP; s++) {
        cpa_wait0();
        __syncthreads();
        if (s + 1 < NSTEP) {
            int nb = (s + 1) & 1;
            int k0 = (s + 1) * 32;
            cpa16(Adst0[nb], Asrc0 + k0); cpa16(Adst1[nb], Asrc1 + k0);
            cpa16(BdstL[nb], BsrcL + k0); cpa16(BdstG[nb], BsrcG + k0);
            cpa_commit();
        }
        int buf = s & 1;
        const uint32_t* A32 = reinterpret_cast<const uint32_t*>(&As[buf][0]);
        const uint32_t* BL  = reinterpret_cast<const uint32_t*>(&Bs[buf][0][0]);
        const uint32_t* BG  = reinterpret_cast<const uint32_t*>(&Bs[buf][1][0]);
        #pragma unroll
        for (int kk = 0; kk < 2; kk++) {
            int kw = kk * 8;
            uint32_t afr[2][4];
            #pragma unroll
            for (int mf = 0; mf < 2; mf++) {
                int mo = warp_m*32 + mf*16;
                afr[mf][0] = A32[(mo + gq)     * 20 + kw + tg];
                afr[mf][1] = A32[(mo + gq + 8) * 20 + kw + tg];
                afr[mf][2] = A32[(mo + gq)     * 20 + kw + tg + 4];
                afr[mf][3] = A32[(mo + gq + 8) * 20 + kw + tg + 4];
            }
            uint32_t bfL[4][2], bfG[4][2];
            #pragma unroll
            for (int nf = 0; nf < 4; nf++) {
                int no = warp_n*32 + nf*8;
                bfL[nf][0] = BL[(no + gq) * 20 + kw + tg];
                bfL[nf][1] = BL[(no + gq) * 20 + kw + tg + 4];
                bfG[nf][0] = BG[(no + gq) * 20 + kw + tg];
                bfG[nf][1] = BG[(no + gq) * 20 + kw + tg + 4];
            }
            #pragma unroll
            for (int mf = 0; mf < 2; mf++)
                #pragma unroll
                for (int nf = 0; nf < 4; nf++) {
                    MMA16816(aL[mf][nf], afr[mf], bfL[nf]);
                    MMA16816(aG[mf][nf], afr[mf], bfG[nf]);
                }
        }
    }

    // epilogue
    #pragma unroll
    for (int mf = 0; mf < 2; mf++) {
        #pragma unroll
        for (int nf = 0; nf < 4; nf++) {
            int rb = mtile*128 + warp_m*32 + mf*16 + gq;
            int cb = ntile*64 + warp_n*32 + nf*8 + tg*2;
            if (MODE == 0) {
                float2 bl2 = *reinterpret_cast<const float2*>(bl + cb);
                float2 bg2 = *reinterpret_cast<const float2*>(bg + cb);
                #pragma unroll
                for (int h = 0; h < 2; h++) {
                    int r = rb + h*8;
                    float2 u, g;
                    u.x = aL[mf][nf][h*2 + 0] + bl2.x;
                    u.y = aL[mf][nf][h*2 + 1] + bl2.y;
                    g.x = aG[mf][nf][h*2 + 0] + bg2.x;
                    g.y = aG[mf][nf][h*2 + 1] + bg2.y;
                    *reinterpret_cast<float2*>(g_capU + (size_t)r * DD + cb) = u;
                    *reinterpret_cast<float2*>(g_capG + (size_t)r * DD + cb) = g;
                }
            } else {
                #pragma unroll
                for (int h = 0; h < 2; h++) {
                    int r = rb + h*8;
                    int ccap = r / (II*TT), t = r % TT;
                    size_t crow = ((size_t)(ccap*TT + t)) * DD + cb;
                    float2 cp = *reinterpret_cast<const float2*>(cap + crow);
                    float2 cu = *reinterpret_cast<const float2*>(g_capU + crow);
                    float2 cg = *reinterpret_cast<const float2*>(g_capG + crow);
                    float u0 = tanhf(aL[mf][nf][h*2 + 0] + cu.x);
                    float u1 = tanhf(aL[mf][nf][h*2 + 1] + cu.y);
                    float s0 = 1.f / (1.f + expf(-(aG[mf][nf][h*2 + 0] + cg.x)));
                    float s1 = 1.f / (1.f + expf(-(aG[mf][nf][h*2 + 1] + cg.y)));
                    float2 o;
                    o.x = cp.x * s0 + u0 * (1.f - s0);
                    o.y = cp.y * s1 + u1 * (1.f - s1);
                    *reinterpret_cast<float2*>(g_q1 + (size_t)r * DD + cb) = o;
                }
            }
        }
    }
}

// ---------------- launch ----------------
extern "C" void kernel_launch(void* const* d_in, const int* in_sizes, int n_in,
                              void* d_out, int out_size) {
    (void)in_sizes; (void)n_in; (void)out_size;
    const float* img    = (const float*)d_in[0];
    const float* cap    = (const float*)d_in[1];
    const float* W_lin  = (const float*)d_in[2];
    const float* b_lin  = (const float*)d_in[3];
    const float* W_gate = (const float*)d_in[4];
    const float* b_gate = (const float*)d_in[5];
    float* out = (float*)d_out;

    const int SMEM_ATTN = (RR*DD + RR*TT + TT*RR) * (int)sizeof(float);
    cudaFuncSetAttribute(attn_kernel, cudaFuncAttributeMaxDynamicSharedMemorySize, SMEM_ATTN);

    prep_wt<<<dim3(32, 64), dim3(32, 8)>>>(W_lin, 0);
    prep_wt<<<dim3(32, 64), dim3(32, 8)>>>(W_gate, 1);
    prep_capb<<<1280, 256>>>(cap);

    // caption-side half of the gated GEMM: image-independent, done once
    gemm_dual<0><<<dim3(16, 10), 256>>>(b_lin, b_gate, cap);

    // iteration 0
    attn_kernel<<<CC*II, 256, SMEM_ATTN>>>(img, cap, 0);
    sim_kernel<<<CC*II, 256>>>(cap, out, 0);

    // gated memory (only live once: iteration 1's update is dead code)
    gemm_dual<1><<<dim3(16, 320), 256>>>(b_lin, b_gate, cap);

    // iteration 1
    attn_kernel<<<CC*II, 256, SMEM_ATTN>>>(img, cap, 1);
    sim_kernel<<<CC*II, 256>>>(cap, out, 1);
}

// round 15
// speedup vs baseline: 1.4850x; 1.0744x over previous
#include <cuda_runtime.h>
#include <cuda_bf16.h>
#include <cstdint>
#include <math.h>

#define CC 32
#define II 32
#define TT 40
#define RR 36
#define DD 1024
#define MM (CC*II*TT)     /* 40960 */
#define KK 2048
#define PITCH 40          /* bf16 elems per smem row (32 data + 8 pad) */

// ---------------- device scratch (no cudaMalloc allowed) ----------------
__device__ __nv_bfloat16 g_wcb[(size_t)MM*DD];        // weightedContext bf16 (GEMM A)
__device__ float g_q1[(size_t)MM*DD];                 // updated query
__device__ __nv_bfloat16 g_capb[(size_t)CC*TT*DD];    // caption bf16
__device__ float g_capU[(size_t)CC*TT*DD];            // cap @ W_lin_top + b_lin
__device__ float g_capG[(size_t)CC*TT*DD];            // cap @ W_gate_top + b_gate
__device__ __nv_bfloat16 g_WtL[(size_t)DD*KK];        // W_lin^T  [n][k]
__device__ __nv_bfloat16 g_WtG[(size_t)DD*KK];        // W_gate^T [n][k]

// ---------------- helpers ----------------
__device__ __forceinline__ uint32_t smem_u32(const void* p) {
    uint32_t a;
    asm("{ .reg .u64 t; cvta.to.shared.u64 t, %1; cvt.u32.u64 %0, t; }" : "=r"(a) : "l"(p));
    return a;
}
__device__ __forceinline__ void cpa16(uint32_t d, const void* s) {
    asm volatile("cp.async.cg.shared.global [%0], [%1], 16;" :: "r"(d), "l"(s));
}
__device__ __forceinline__ void cpa_commit() { asm volatile("cp.async.commit_group;" ::: "memory"); }
__device__ __forceinline__ void cpa_wait0()  { asm volatile("cp.async.wait_group 0;" ::: "memory"); }
__device__ __forceinline__ void cpa_wait2()  { asm volatile("cp.async.wait_group 2;" ::: "memory"); }

#define MMA16816(d, a, b) \
  asm volatile("mma.sync.aligned.m16n8k16.row.col.f32.bf16.bf16.f32 " \
    "{%0,%1,%2,%3}, {%4,%5,%6,%7}, {%8,%9}, {%0,%1,%2,%3};" \
    : "+f"((d)[0]), "+f"((d)[1]), "+f"((d)[2]), "+f"((d)[3]) \
    : "r"((a)[0]), "r"((a)[1]), "r"((a)[2]), "r"((a)[3]), "r"((b)[0]), "r"((b)[1]))

// ---------------- prep: W^T -> bf16 ----------------
__global__ void prep_wt(const float* __restrict__ W, int which) {
    __shared__ float tile[32][33];
    __nv_bfloat16* Wt = which ? g_WtG : g_WtL;
    int n0 = blockIdx.x * 32;
    int k0 = blockIdx.y * 32;
    int tx = threadIdx.x, ty = threadIdx.y;  // (32, 8)
    #pragma unroll
    for (int j = 0; j < 4; j++)
        tile[ty + j*8][tx] = W[(size_t)(k0 + ty + j*8) * DD + n0 + tx];
    __syncthreads();
    #pragma unroll
    for (int j = 0; j < 4; j++)
        Wt[(size_t)(n0 + ty + j*8) * KK + k0 + tx] =
            __float2bfloat16(tile[tx][ty + j*8]);
}

// ---------------- prep: caption fp32 -> bf16 ----------------
__global__ void prep_capb(const float* __restrict__ cap) {
    size_t idx = (size_t)blockIdx.x * 256 + threadIdx.x;   // float4 index
    float4 v = reinterpret_cast<const float4*>(cap)[idx];
    __nv_bfloat162 lo = __floats2bfloat162_rn(v.x, v.y);
    __nv_bfloat162 hi = __floats2bfloat162_rn(v.z, v.w);
    __nv_bfloat162* dst = reinterpret_cast<__nv_bfloat162*>(g_capb + idx*4);
    dst[0] = lo; dst[1] = hi;
}

// ---------------- fused attention + similarity step (512 threads) ----------------
__global__ __launch_bounds__(512)
void attn_kernel(const float* __restrict__ img, const float* __restrict__ cap,
                 float* __restrict__ out, int iter) {
    extern __shared__ float sm[];
    float* imgS  = sm;                        // 36*1024
    float* attn  = sm + RR*DD;                // [36][40] r-major
    float* attn2 = attn + RR*TT;              // [40][36] t-major
    float* pdot  = attn2 + TT*RR;             // [40][16]
    float* pna   = pdot + TT*16;
    float* pnb   = pna + TT*16;
    float* cosb  = pnb + TT*16;               // [40]
    int tid = threadIdx.x, lane = tid & 31, w = tid >> 5;   // 16 warps
    int pair = blockIdx.x, c = pair >> 5, i = pair & 31;

    // phase A: load image tile + zero sim partials
    {
        const float4* imgv = reinterpret_cast<const float4*>(img) + (size_t)i * RR * 256;
        float4* img4 = reinterpret_cast<float4*>(imgS);
        for (int idx = tid; idx < RR*256; idx += 512)
            img4[idx] = imgv[idx];
        for (int idx = tid; idx < TT*16*3; idx += 512)
            pdot[idx] = 0.f;
    }
    __syncthreads();

    // phase B: attn[r][t] = img[r] . q[t]   (2 t rows per warp)
    {
        const float4* qv = iter ? reinterpret_cast<const float4*>(g_q1)
                                : reinterpret_cast<const float4*>(cap);
        const float4* img4 = reinterpret_cast<const float4*>(imgS);
        for (int pass = 0; pass < 2; pass++) {
            int tA = (pass == 0) ? 2*w : 32 + 2*w;
            bool active = (pass == 0) || (w < 4);
            if (active) {
                int tB = tA + 1;
                int rA = iter ? (pair*TT + tA) : (c*TT + tA);
                int rB = iter ? (pair*TT + tB) : (c*TT + tB);
                size_t qa = (size_t)rA * 256, qb = (size_t)rB * 256;
                float4 Qa[8], Qb[8];
                #pragma unroll
                for (int j = 0; j < 8; j++) { Qa[j] = qv[qa + j*32 + lane]; Qb[j] = qv[qb + j*32 + lane]; }
                for (int r = 0; r < RR; r++) {
                    float pa = 0.f, pb = 0.f;
                    #pragma unroll
                    for (int j = 0; j < 8; j++) {
                        float4 v = img4[r*256 + j*32 + lane];
                        pa += v.x*Qa[j].x + v.y*Qa[j].y + v.z*Qa[j].z + v.w*Qa[j].w;
                        pb += v.x*Qb[j].x + v.y*Qb[j].y + v.z*Qb[j].z + v.w*Qb[j].w;
                    }
                    #pragma unroll
                    for (int o = 16; o; o >>= 1) {
                        pa += __shfl_xor_sync(0xffffffffu, pa, o);
                        pb += __shfl_xor_sync(0xffffffffu, pb, o);
                    }
                    if (lane == 0) { attn[r*TT + tA] = pa; attn[r*TT + tB] = pb; }
                }
            }
        }
    }
    __syncthreads();

    // phase C: leaky relu + l2norm over t (per r)
    if (tid < RR) {
        float s = 0.f;
        #pragma unroll 8
        for (int t = 0; t < TT; t++) {
            float v = attn[tid*TT + t];
            v = (v > 0.f) ? v : 0.1f * v;
            attn[tid*TT + t] = v;
            s += v * v;
        }
        float inv = 1.f / (sqrtf(s) + 1e-8f);
        #pragma unroll 8
        for (int t = 0; t < TT; t++) attn[tid*TT + t] *= inv;
    }
    __syncthreads();

    // phase D: softmax over r (per t), temperature 9
    if (tid < TT) {
        float mx = -1e30f;
        for (int r = 0; r < RR; r++) mx = fmaxf(mx, attn[r*TT + tid]);
        float s = 0.f;
        for (int r = 0; r < RR; r++) {
            float e = expf(9.0f * (attn[r*TT + tid] - mx));
            attn2[tid*RR + r] = e;
            s += e;
        }
        float inv = 1.f / s;
        for (int r = 0; r < RR; r++) attn2[tid*RR + r] *= inv;
    }
    __syncthreads();

    // phase E: wc[t] = attn2[t] @ img ; fused cosine-sim; bf16 write (iter0 only)
    {
        const float2* img2 = reinterpret_cast<const float2*>(imgS);
        const float2* cap2 = reinterpret_cast<const float2*>(cap);
        int col = tid;   // float2 column 0..511
        for (int tb = 0; tb < 5; tb++) {
            float2 acc[8];
            #pragma unroll
            for (int j = 0; j < 8; j++) acc[j] = make_float2(0.f, 0.f);
            for (int r = 0; r < RR; r++) {
                float2 v = img2[r*512 + col];
                #pragma unroll
                for (int j = 0; j < 8; j++) {
                    float a = attn2[(tb*8 + j)*RR + r];
                    acc[j].x += v.x*a; acc[j].y += v.y*a;
                }
            }
            #pragma unroll
            for (int j = 0; j < 8; j++) {
                int t = tb*8 + j;
                if (iter == 0) {
                    size_t m = (size_t)pair*TT + t;
                    *reinterpret_cast<__nv_bfloat162*>(g_wcb + m*DD + (size_t)col*2) =
                        __floats2bfloat162_rn(acc[j].x, acc[j].y);
                }
                float2 cp = cap2[((size_t)(c*TT + t))*512 + col];
                float dot = cp.x*acc[j].x + cp.y*acc[j].y;
                float nb  = acc[j].x*acc[j].x + acc[j].y*acc[j].y;
                float na  = cp.x*cp.x + cp.y*cp.y;
                #pragma unroll
                for (int o = 16; o; o >>= 1) {
                    dot += __shfl_xor_sync(0xffffffffu, dot, o);
                    nb  += __shfl_xor_sync(0xffffffffu, nb, o);
                    na  += __shfl_xor_sync(0xffffffffu, na, o);
                }
                if (lane == 0) {
                    pdot[t*16 + w] = dot;
                    pna [t*16 + w] = na;
                    pnb [t*16 + w] = nb;
                }
            }
        }
    }
    __syncthreads();

    if (tid < TT) {
        float dot = 0.f, na = 0.f, nb = 0.f;
        #pragma unroll
        for (int k = 0; k < 16; k++) {
            dot += pdot[tid*16 + k];
            na  += pna [tid*16 + k];
            nb  += pnb [tid*16 + k];
        }
        cosb[tid] = dot / fmaxf(sqrtf(na) * sqrtf(nb), 1e-8f);
    }
    __syncthreads();
    if (tid == 0) {
        float s = 0.f;
        for (int t = 0; t < TT; t++) s += cosb[t];
        s *= (1.0f / TT);
        size_t o = (size_t)i * CC + c;
        out[o] = iter ? (out[o] + s) : s;
    }
}

// ---------------- small GEMM: capU/capG = cap @ W_top + bias (M=1280) ----------------
template<int MODE>
__global__ __launch_bounds__(256)
void gemm_dual(const float* __restrict__ bl, const float* __restrict__ bg,
               const float* __restrict__ cap) {
    __shared__ __align__(16) __nv_bfloat16 As[2][128*PITCH];
    __shared__ __align__(16) __nv_bfloat16 Bs[2][2][64*PITCH];
    int tid = threadIdx.x, lane = tid & 31, wid = tid >> 5;
    int warp_m = wid & 3, warp_n = wid >> 2;
    int gq = lane >> 2, tg = lane & 3;
    int ntile = blockIdx.x, mtile = blockIdx.y;

    float aL[2][4][4], aG[2][4][4];
    #pragma unroll
    for (int mf = 0; mf < 2; mf++)
        #pragma unroll
        for (int nf = 0; nf < 4; nf++)
            #pragma unroll
            for (int q = 0; q < 4; q++) { aL[mf][nf][q] = 0.f; aG[mf][nf][q] = 0.f; }

    int a_r0 = tid >> 2,         a_c0 = tid & 3;
    int a_r1 = (tid + 256) >> 2, a_c1 = tid & 3;
    int b_r  = tid >> 2,         b_c  = tid & 3;
    const __nv_bfloat16* Asrc0 = g_capb + ((size_t)(mtile*128 + a_r0))*DD + a_c0*8;
    const __nv_bfloat16* Asrc1 = g_capb + ((size_t)(mtile*128 + a_r1))*DD + a_c1*8;
    const __nv_bfloat16* BsrcL = g_WtL + ((size_t)(ntile*64 + b_r))*KK + b_c*8;
    const __nv_bfloat16* BsrcG = g_WtG + ((size_t)(ntile*64 + b_r))*KK + b_c*8;
    uint32_t Adst0[2], Adst1[2], BdstL[2], BdstG[2];
    #pragma unroll
    for (int b = 0; b < 2; b++) {
        Adst0[b] = smem_u32(&As[b][a_r0*PITCH + a_c0*8]);
        Adst1[b] = smem_u32(&As[b][a_r1*PITCH + a_c1*8]);
        BdstL[b] = smem_u32(&Bs[b][0][b_r*PITCH + b_c*8]);
        BdstG[b] = smem_u32(&Bs[b][1][b_r*PITCH + b_c*8]);
    }

    cpa16(Adst0[0], Asrc0); cpa16(Adst1[0], Asrc1);
    cpa16(BdstL[0], BsrcL); cpa16(BdstG[0], BsrcG);
    cpa_commit();

    const int NSTEP = 32;
    for (int s = 0; s < NSTEP; s++) {
        cpa_wait0();
        __syncthreads();
        if (s + 1 < NSTEP) {
            int nb = (s + 1) & 1;
            int k0 = (s + 1) * 32;
            cpa16(Adst0[nb], Asrc0 + k0); cpa16(Adst1[nb], Asrc1 + k0);
            cpa16(BdstL[nb], BsrcL + k0); cpa16(BdstG[nb], BsrcG + k0);
            cpa_commit();
        }
        int buf = s & 1;
        const uint32_t* A32 = reinterpret_cast<const uint32_t*>(&As[buf][0]);
        const uint32_t* BL  = reinterpret_cast<const uint32_t*>(&Bs[buf][0][0]);
        const uint32_t* BG  = reinterpret_cast<const uint32_t*>(&Bs[buf][1][0]);
        #pragma unroll
        for (int kk = 0; kk < 2; kk++) {
            int kw = kk * 8;
            uint32_t afr[2][4];
            #pragma unroll
            for (int mf = 0; mf < 2; mf++) {
                int mo = warp_m*32 + mf*16;
                afr[mf][0] = A32[(mo + gq)     * 20 + kw + tg];
                afr[mf][1] = A32[(mo + gq + 8) * 20 + kw + tg];
                afr[mf][2] = A32[(mo + gq)     * 20 + kw + tg + 4];
                afr[mf][3] = A32[(mo + gq + 8) * 20 + kw + tg + 4];
            }
            uint32_t bfL[4][2], bfG[4][2];
            #pragma unroll
            for (int nf = 0; nf < 4; nf++) {
                int no = warp_n*32 + nf*8;
                bfL[nf][0] = BL[(no + gq) * 20 + kw + tg];
                bfL[nf][1] = BL[(no + gq) * 20 + kw + tg + 4];
                bfG[nf][0] = BG[(no + gq) * 20 + kw + tg];
                bfG[nf][1] = BG[(no + gq) * 20 + kw + tg + 4];
            }
            #pragma unroll
            for (int mf = 0; mf < 2; mf++)
                #pragma unroll
                for (int nf = 0; nf < 4; nf++) {
                    MMA16816(aL[mf][nf], afr[mf], bfL[nf]);
                    MMA16816(aG[mf][nf], afr[mf], bfG[nf]);
                }
        }
    }

    #pragma unroll
    for (int mf = 0; mf < 2; mf++) {
        #pragma unroll
        for (int nf = 0; nf < 4; nf++) {
            int rb = mtile*128 + warp_m*32 + mf*16 + gq;
            int cb = ntile*64 + warp_n*32 + nf*8 + tg*2;
            float2 bl2 = *reinterpret_cast<const float2*>(bl + cb);
            float2 bg2 = *reinterpret_cast<const float2*>(bg + cb);
            #pragma unroll
            for (int h = 0; h < 2; h++) {
                int r = rb + h*8;
                float2 u, g;
                u.x = aL[mf][nf][h*2 + 0] + bl2.x;
                u.y = aL[mf][nf][h*2 + 1] + bl2.y;
                g.x = aG[mf][nf][h*2 + 0] + bg2.x;
                g.y = aG[mf][nf][h*2 + 1] + bg2.y;
                *reinterpret_cast<float2*>(g_capU + (size_t)r * DD + cb) = u;
                *reinterpret_cast<float2*>(g_capG + (size_t)r * DD + cb) = g;
            }
        }
    }
}

// ---------------- main GEMM: 4-stage cp.async ring, fused gated epilogue ----------------
#define ABUF (128*PITCH)            /* elems per A stage = 5120 */
#define BBUF (2*64*PITCH)           /* elems per B stage = 5120 */
#define BOFF (4*ABUF)               /* B region start    = 20480 */

__global__ __launch_bounds__(256)
void gemm_main(const float* __restrict__ cap) {
    extern __shared__ __nv_bfloat16 dsm[];
    int tid = threadIdx.x, lane = tid & 31, wid = tid >> 5;
    int warp_m = wid & 3, warp_n = wid >> 2;
    int gq = lane >> 2, tg = lane & 3;
    int ntile = blockIdx.x, mtile = blockIdx.y;

    float aL[2][4][4], aG[2][4][4];
    #pragma unroll
    for (int mf = 0; mf < 2; mf++)
        #pragma unroll
        for (int nf = 0; nf < 4; nf++)
            #pragma unroll
            for (int q = 0; q < 4; q++) { aL[mf][nf][q] = 0.f; aG[mf][nf][q] = 0.f; }

    int a_r0 = tid >> 2,         a_c0 = tid & 3;
    int a_r1 = (tid + 256) >> 2, a_c1 = tid & 3;
    int b_r  = tid >> 2,         b_c  = tid & 3;
    const __nv_bfloat16* Asrc0 = g_wcb + ((size_t)(mtile*128 + a_r0))*DD + a_c0*8;
    const __nv_bfloat16* Asrc1 = g_wcb + ((size_t)(mtile*128 + a_r1))*DD + a_c1*8;
    const __nv_bfloat16* BsrcL = g_WtL + ((size_t)(ntile*64 + b_r))*KK + DD + b_c*8;
    const __nv_bfloat16* BsrcG = g_WtG + ((size_t)(ntile*64 + b_r))*KK + DD + b_c*8;
    uint32_t Adst0[4], Adst1[4], BdstL[4], BdstG[4];
    #pragma unroll
    for (int b = 0; b < 4; b++) {
        Adst0[b] = smem_u32(dsm + b*ABUF + a_r0*PITCH + a_c0*8);
        Adst1[b] = smem_u32(dsm + b*ABUF + a_r1*PITCH + a_c1*8);
        BdstL[b] = smem_u32(dsm + BOFF + b*BBUF + b_r*PITCH + b_c*8);
        BdstG[b] = smem_u32(dsm + BOFF + b*BBUF + 64*PITCH + b_r*PITCH + b_c*8);
    }

    // prefetch 3 stages
    #pragma unroll
    for (int p = 0; p < 3; p++) {
        int k0 = p * 32;
        cpa16(Adst0[p], Asrc0 + k0); cpa16(Adst1[p], Asrc1 + k0);
        cpa16(BdstL[p], BsrcL + k0); cpa16(BdstG[p], BsrcG + k0);
        cpa_commit();
    }

    const int NSTEP = 32;
    for (int s = 0; s < NSTEP; s++) {
        cpa_wait2();
        __syncthreads();
        if (s + 3 < NSTEP) {
            int b = (s + 3) & 3;
            int k0 = (s + 3) * 32;
            cpa16(Adst0[b], Asrc0 + k0); cpa16(Adst1[b], Asrc1 + k0);
            cpa16(BdstL[b], BsrcL + k0); cpa16(BdstG[b], BsrcG + k0);
        }
        cpa_commit();   // always commit: keeps group counting uniform for wait_group 2
        int buf = s & 3;
        const uint32_t* A32 = reinterpret_cast<const uint32_t*>(dsm + buf*ABUF);
        const uint32_t* BL  = reinterpret_cast<const uint32_t*>(dsm + BOFF + buf*BBUF);
        const uint32_t* BG  = BL + (64*PITCH)/2;
        #pragma unroll
        for (int kk = 0; kk < 2; kk++) {
            int kw = kk * 8;
            uint32_t afr[2][4];
            #pragma unroll
            for (int mf = 0; mf < 2; mf++) {
                int mo = warp_m*32 + mf*16;
                afr[mf][0] = A32[(mo + gq)     * 20 + kw + tg];
                afr[mf][1] = A32[(mo + gq + 8) * 20 + kw + tg];
                afr[mf][2] = A32[(mo + gq)     * 20 + kw + tg + 4];
                afr[mf][3] = A32[(mo + gq + 8) * 20 + kw + tg + 4];
            }
            uint32_t bfL[4][2], bfG[4][2];
            #pragma unroll
            for (int nf = 0; nf < 4; nf++) {
                int no = warp_n*32 + nf*8;
                bfL[nf][0] = BL[(no + gq) * 20 + kw + tg];
                bfL[nf][1] = BL[(no + gq) * 20 + kw + tg + 4];
                bfG[nf][0] = BG[(no + gq) * 20 + kw + tg];
                bfG[nf][1] = BG[(no + gq) * 20 + kw + tg + 4];
            }
            #pragma unroll
            for (int mf = 0; mf < 2; mf++)
                #pragma unroll
                for (int nf = 0; nf < 4; nf++) {
                    MMA16816(aL[mf][nf], afr[mf], bfL[nf]);
                    MMA16816(aG[mf][nf], afr[mf], bfG[nf]);
                }
        }
    }

    // gated epilogue: q1 = cap*sig(g) + tanh(u)*(1-sig(g))
    #pragma unroll
    for (int mf = 0; mf < 2; mf++) {
        #pragma unroll
        for (int nf = 0; nf < 4; nf++) {
            int rb = mtile*128 + warp_m*32 + mf*16 + gq;
            int cb = ntile*64 + warp_n*32 + nf*8 + tg*2;
            #pragma unroll
            for (int h = 0; h < 2; h++) {
                int r = rb + h*8;
                int ccap = r / (II*TT), t = r % TT;
                size_t crow = ((size_t)(ccap*TT + t)) * DD + cb;
                float2 cp = *reinterpret_cast<const float2*>(cap + crow);
                float2 cu = *reinterpret_cast<const float2*>(g_capU + crow);
                float2 cg = *reinterpret_cast<const float2*>(g_capG + crow);
                float u0 = tanhf(aL[mf][nf][h*2 + 0] + cu.x);
                float u1 = tanhf(aL[mf][nf][h*2 + 1] + cu.y);
                float s0 = 1.f / (1.f + expf(-(aG[mf][nf][h*2 + 0] + cg.x)));
                float s1 = 1.f / (1.f + expf(-(aG[mf][nf][h*2 + 1] + cg.y)));
                float2 o;
                o.x = cp.x * s0 + u0 * (1.f - s0);
                o.y = cp.y * s1 + u1 * (1.f - s1);
                *reinterpret_cast<float2*>(g_q1 + (size_t)r * DD + cb) = o;
            }
        }
    }
}

// ---------------- launch ----------------
extern "C" void kernel_launch(void* const* d_in, const int* in_sizes, int n_in,
                              void* d_out, int out_size) {
    (void)in_sizes; (void)n_in; (void)out_size;
    const float* img    = (const float*)d_in[0];
    const float* cap    = (const float*)d_in[1];
    const float* W_lin  = (const float*)d_in[2];
    const float* b_lin  = (const float*)d_in[3];
    const float* W_gate = (const float*)d_in[4];
    const float* b_gate = (const float*)d_in[5];
    float* out = (float*)d_out;

    const int SMEM_ATTN = (RR*DD + RR*TT + TT*RR + 3*TT*16 + TT) * (int)sizeof(float); // 166816
    const int SMEM_GEMM = (BOFF + 4*BBUF) * (int)sizeof(__nv_bfloat16);                // 81920
    cudaFuncSetAttribute(attn_kernel, cudaFuncAttributeMaxDynamicSharedMemorySize, SMEM_ATTN);
    cudaFuncSetAttribute(gemm_main,   cudaFuncAttributeMaxDynamicSharedMemorySize, SMEM_GEMM);

    prep_wt<<<dim3(32, 64), dim3(32, 8)>>>(W_lin, 0);
    prep_wt<<<dim3(32, 64), dim3(32, 8)>>>(W_gate, 1);
    prep_capb<<<1280, 256>>>(cap);

    // caption-side half of the gated GEMM: image-independent, done once
    gemm_dual<0><<<dim3(16, 10), 256>>>(b_lin, b_gate, cap);

    // iteration 0: attn + fused sim (writes score) + bf16 wc for GEMM
    attn_kernel<<<CC*II, 512, SMEM_ATTN>>>(img, cap, out, 0);

    // gated memory (only live once: iteration 1's update is dead code)
    gemm_main<<<dim3(16, 320), 256, SMEM_GEMM>>>(cap);

    // iteration 1: attn + fused sim (accumulates score)
    attn_kernel<<<CC*II, 512, SMEM_ATTN>>>(img, cap, out, 1);
}

// round 17
// speedup vs baseline: 1.5610x; 1.0512x over previous
#include <cuda_runtime.h>
#include <cuda_bf16.h>
#include <cstdint>
#include <math.h>

#define CC 32
#define II 32
#define TT 40
#define RR 36
#define DD 1024
#define MM (CC*II*TT)     /* 40960 */
#define KK 2048
#define PITCH 40          /* bf16 elems per smem row (32 data + 8 pad) */

// ---------------- device scratch (no cudaMalloc allowed) ----------------
__device__ __nv_bfloat16 g_wcb[(size_t)MM*DD];        // weightedContext bf16 (GEMM A)
__device__ float g_q1[(size_t)MM*DD];                 // updated query
__device__ __nv_bfloat16 g_capb[(size_t)CC*TT*DD];    // caption bf16
__device__ float g_capU[(size_t)CC*TT*DD];            // cap @ W_lin_top + b_lin
__device__ float g_capG[(size_t)CC*TT*DD];            // cap @ W_gate_top + b_gate
__device__ __nv_bfloat16 g_WtL[(size_t)DD*KK];        // W_lin^T  [n][k]
__device__ __nv_bfloat16 g_WtG[(size_t)DD*KK];        // W_gate^T [n][k]

// ---------------- helpers ----------------
__device__ __forceinline__ uint32_t smem_u32(const void* p) {
    uint32_t a;
    asm("{ .reg .u64 t; cvta.to.shared.u64 t, %1; cvt.u32.u64 %0, t; }" : "=r"(a) : "l"(p));
    return a;
}
__device__ __forceinline__ void cpa16(uint32_t d, const void* s) {
    asm volatile("cp.async.cg.shared.global [%0], [%1], 16;" :: "r"(d), "l"(s));
}
__device__ __forceinline__ void cpa_commit() { asm volatile("cp.async.commit_group;" ::: "memory"); }
__device__ __forceinline__ void cpa_wait0()  { asm volatile("cp.async.wait_group 0;" ::: "memory"); }
__device__ __forceinline__ void cpa_wait2()  { asm volatile("cp.async.wait_group 2;" ::: "memory"); }

#define MMA16816(d, a, b) \
  asm volatile("mma.sync.aligned.m16n8k16.row.col.f32.bf16.bf16.f32 " \
    "{%0,%1,%2,%3}, {%4,%5,%6,%7}, {%8,%9}, {%0,%1,%2,%3};" \
    : "+f"((d)[0]), "+f"((d)[1]), "+f"((d)[2]), "+f"((d)[3]) \
    : "r"((a)[0]), "r"((a)[1]), "r"((a)[2]), "r"((a)[3]), "r"((b)[0]), "r"((b)[1]))

#define LDSM4(r, addr) \
  asm volatile("ldmatrix.sync.aligned.m8n8.x4.shared.b16 {%0,%1,%2,%3}, [%4];" \
    : "=r"((r)[0]), "=r"((r)[1]), "=r"((r)[2]), "=r"((r)[3]) : "r"(addr))

// ---------------- prep: W^T -> bf16 ----------------
__global__ void prep_wt(const float* __restrict__ W, int which) {
    __shared__ float tile[32][33];
    __nv_bfloat16* Wt = which ? g_WtG : g_WtL;
    int n0 = blockIdx.x * 32;
    int k0 = blockIdx.y * 32;
    int tx = threadIdx.x, ty = threadIdx.y;  // (32, 8)
    #pragma unroll
    for (int j = 0; j < 4; j++)
        tile[ty + j*8][tx] = W[(size_t)(k0 + ty + j*8) * DD + n0 + tx];
    __syncthreads();
    #pragma unroll
    for (int j = 0; j < 4; j++)
        Wt[(size_t)(n0 + ty + j*8) * KK + k0 + tx] =
            __float2bfloat16(tile[tx][ty + j*8]);
}

// ---------------- prep: caption fp32 -> bf16 ----------------
__global__ void prep_capb(const float* __restrict__ cap) {
    size_t idx = (size_t)blockIdx.x * 256 + threadIdx.x;   // float4 index
    float4 v = reinterpret_cast<const float4*>(cap)[idx];
    __nv_bfloat162 lo = __floats2bfloat162_rn(v.x, v.y);
    __nv_bfloat162 hi = __floats2bfloat162_rn(v.z, v.w);
    __nv_bfloat162* dst = reinterpret_cast<__nv_bfloat162*>(g_capb + idx*4);
    dst[0] = lo; dst[1] = hi;
}

// ---------------- fused attention + similarity step (512 threads) ----------------
__global__ __launch_bounds__(512)
void attn_kernel(const float* __restrict__ img, const float* __restrict__ cap,
                 float* __restrict__ out, int iter) {
    extern __shared__ float sm[];
    float* imgS  = sm;                        // 36*1024
    float* attn  = sm + RR*DD;                // [36][40] r-major
    float* attn2 = attn + RR*TT;              // [40][36] t-major
    float* pdot  = attn2 + TT*RR;             // [40][16]
    float* pna   = pdot + TT*16;
    float* pnb   = pna + TT*16;
    float* cosb  = pnb + TT*16;               // [40]
    int tid = threadIdx.x, lane = tid & 31, w = tid >> 5;   // 16 warps
    int pair = blockIdx.x, c = pair >> 5, i = pair & 31;

    // phase A: load image tile + zero sim partials
    {
        const float4* imgv = reinterpret_cast<const float4*>(img) + (size_t)i * RR * 256;
        float4* img4 = reinterpret_cast<float4*>(imgS);
        for (int idx = tid; idx < RR*256; idx += 512)
            img4[idx] = imgv[idx];
        for (int idx = tid; idx < TT*16*3; idx += 512)
            pdot[idx] = 0.f;
    }
    __syncthreads();

    // phase B: attn[r][t] = img[r] . q[t]   (2 t rows per warp)
    {
        const float4* qv = iter ? reinterpret_cast<const float4*>(g_q1)
                                : reinterpret_cast<const float4*>(cap);
        const float4* img4 = reinterpret_cast<const float4*>(imgS);
        for (int pass = 0; pass < 2; pass++) {
            int tA = (pass == 0) ? 2*w : 32 + 2*w;
            bool active = (pass == 0) || (w < 4);
            if (active) {
                int tB = tA + 1;
                int rA = iter ? (pair*TT + tA) : (c*TT + tA);
                int rB = iter ? (pair*TT + tB) : (c*TT + tB);
                size_t qa = (size_t)rA * 256, qb = (size_t)rB * 256;
                float4 Qa[8], Qb[8];
                #pragma unroll
                for (int j = 0; j < 8; j++) { Qa[j] = qv[qa + j*32 + lane]; Qb[j] = qv[qb + j*32 + lane]; }
                for (int r = 0; r < RR; r++) {
                    float pa = 0.f, pb = 0.f;
                    #pragma unroll
                    for (int j = 0; j < 8; j++) {
                        float4 v = img4[r*256 + j*32 + lane];
                        pa += v.x*Qa[j].x + v.y*Qa[j].y + v.z*Qa[j].z + v.w*Qa[j].w;
                        pb += v.x*Qb[j].x + v.y*Qb[j].y + v.z*Qb[j].z + v.w*Qb[j].w;
                    }
                    #pragma unroll
                    for (int o = 16; o; o >>= 1) {
                        pa += __shfl_xor_sync(0xffffffffu, pa, o);
                        pb += __shfl_xor_sync(0xffffffffu, pb, o);
                    }
                    if (lane == 0) { attn[r*TT + tA] = pa; attn[r*TT + tB] = pb; }
                }
            }
        }
    }
    __syncthreads();

    // phase C: leaky relu + l2norm over t (per r)
    if (tid < RR) {
        float s = 0.f;
        #pragma unroll 8
        for (int t = 0; t < TT; t++) {
            float v = attn[tid*TT + t];
            v = (v > 0.f) ? v : 0.1f * v;
            attn[tid*TT + t] = v;
            s += v * v;
        }
        float inv = 1.f / (sqrtf(s) + 1e-8f);
        #pragma unroll 8
        for (int t = 0; t < TT; t++) attn[tid*TT + t] *= inv;
    }
    __syncthreads();

    // phase D: softmax over r (per t), temperature 9
    if (tid < TT) {
        float mx = -1e30f;
        for (int r = 0; r < RR; r++) mx = fmaxf(mx, attn[r*TT + tid]);
        float s = 0.f;
        for (int r = 0; r < RR; r++) {
            float e = expf(9.0f * (attn[r*TT + tid] - mx));
            attn2[tid*RR + r] = e;
            s += e;
        }
        float inv = 1.f / s;
        for (int r = 0; r < RR; r++) attn2[tid*RR + r] *= inv;
    }
    __syncthreads();

    // phase E: wc[t] = attn2[t] @ img ; fused cosine-sim; bf16 write (iter0 only)
    {
        const float2* img2 = reinterpret_cast<const float2*>(imgS);
        const float2* cap2 = reinterpret_cast<const float2*>(cap);
        int col = tid;   // float2 column 0..511
        for (int tb = 0; tb < 5; tb++) {
            float2 acc[8];
            #pragma unroll
            for (int j = 0; j < 8; j++) acc[j] = make_float2(0.f, 0.f);
            for (int r = 0; r < RR; r++) {
                float2 v = img2[r*512 + col];
                #pragma unroll
                for (int j = 0; j < 8; j++) {
                    float a = attn2[(tb*8 + j)*RR + r];
                    acc[j].x += v.x*a; acc[j].y += v.y*a;
                }
            }
            #pragma unroll
            for (int j = 0; j < 8; j++) {
                int t = tb*8 + j;
                if (iter == 0) {
                    size_t m = (size_t)pair*TT + t;
                    *reinterpret_cast<__nv_bfloat162*>(g_wcb + m*DD + (size_t)col*2) =
                        __floats2bfloat162_rn(acc[j].x, acc[j].y);
                }
                float2 cp = cap2[((size_t)(c*TT + t))*512 + col];
                float dot = cp.x*acc[j].x + cp.y*acc[j].y;
                float nb  = acc[j].x*acc[j].x + acc[j].y*acc[j].y;
                float na  = cp.x*cp.x + cp.y*cp.y;
                #pragma unroll
                for (int o = 16; o; o >>= 1) {
                    dot += __shfl_xor_sync(0xffffffffu, dot, o);
                    nb  += __shfl_xor_sync(0xffffffffu, nb, o);
                    na  += __shfl_xor_sync(0xffffffffu, na, o);
                }
                if (lane == 0) {
                    pdot[t*16 + w] = dot;
                    pna [t*16 + w] = na;
                    pnb [t*16 + w] = nb;
                }
            }
        }
    }
    __syncthreads();

    if (tid < TT) {
        float dot = 0.f, na = 0.f, nb = 0.f;
        #pragma unroll
        for (int k = 0; k < 16; k++) {
            dot += pdot[tid*16 + k];
            na  += pna [tid*16 + k];
            nb  += pnb [tid*16 + k];
        }
        cosb[tid] = dot / fmaxf(sqrtf(na) * sqrtf(nb), 1e-8f);
    }
    __syncthreads();
    if (tid == 0) {
        float s = 0.f;
        for (int t = 0; t < TT; t++) s += cosb[t];
        s *= (1.0f / TT);
        size_t o = (size_t)i * CC + c;
        out[o] = iter ? (out[o] + s) : s;
    }
}

// ---------------- small GEMM: capU/capG = cap @ W_top + bias (M=1280) ----------------
__global__ __launch_bounds__(256)
void gemm_cap(const float* __restrict__ bl, const float* __restrict__ bg) {
    __shared__ __align__(16) __nv_bfloat16 As[2][128*PITCH];
    __shared__ __align__(16) __nv_bfloat16 Bs[2][2][64*PITCH];
    int tid = threadIdx.x, lane = tid & 31, wid = tid >> 5;
    int warp_m = wid & 3, warp_n = wid >> 2;
    int gq = lane >> 2, tg = lane & 3;
    int ntile = blockIdx.x, mtile = blockIdx.y;

    float aL[2][4][4], aG[2][4][4];
    #pragma unroll
    for (int mf = 0; mf < 2; mf++)
        #pragma unroll
        for (int nf = 0; nf < 4; nf++)
            #pragma unroll
            for (int q = 0; q < 4; q++) { aL[mf][nf][q] = 0.f; aG[mf][nf][q] = 0.f; }

    int a_r0 = tid >> 2,         a_c0 = tid & 3;
    int a_r1 = (tid + 256) >> 2, a_c1 = tid & 3;
    int b_r  = tid >> 2,         b_c  = tid & 3;
    const __nv_bfloat16* Asrc0 = g_capb + ((size_t)(mtile*128 + a_r0))*DD + a_c0*8;
    const __nv_bfloat16* Asrc1 = g_capb + ((size_t)(mtile*128 + a_r1))*DD + a_c1*8;
    const __nv_bfloat16* BsrcL = g_WtL + ((size_t)(ntile*64 + b_r))*KK + b_c*8;
    const __nv_bfloat16* BsrcG = g_WtG + ((size_t)(ntile*64 + b_r))*KK + b_c*8;
    uint32_t Adst0[2], Adst1[2], BdstL[2], BdstG[2];
    #pragma unroll
    for (int b = 0; b < 2; b++) {
        Adst0[b] = smem_u32(&As[b][a_r0*PITCH + a_c0*8]);
        Adst1[b] = smem_u32(&As[b][a_r1*PITCH + a_c1*8]);
        BdstL[b] = smem_u32(&Bs[b][0][b_r*PITCH + b_c*8]);
        BdstG[b] = smem_u32(&Bs[b][1][b_r*PITCH + b_c*8]);
    }

    cpa16(Adst0[0], Asrc0); cpa16(Adst1[0], Asrc1);
    cpa16(BdstL[0], BsrcL); cpa16(BdstG[0], BsrcG);
    cpa_commit();

    const int NSTEP = 32;
    for (int s = 0; s < NSTEP; s++) {
        cpa_wait0();
        __syncthreads();
        if (s + 1 < NSTEP) {
            int nb = (s + 1) & 1;
            int k0 = (s + 1) * 32;
            cpa16(Adst0[nb], Asrc0 + k0); cpa16(Adst1[nb], Asrc1 + k0);
            cpa16(BdstL[nb], BsrcL + k0); cpa16(BdstG[nb], BsrcG + k0);
            cpa_commit();
        }
        int buf = s & 1;
        const uint32_t* A32 = reinterpret_cast<const uint32_t*>(&As[buf][0]);
        const uint32_t* BL  = reinterpret_cast<const uint32_t*>(&Bs[buf][0][0]);
        const uint32_t* BG  = reinterpret_cast<const uint32_t*>(&Bs[buf][1][0]);
        #pragma unroll
        for (int kk = 0; kk < 2; kk++) {
            int kw = kk * 8;
            uint32_t afr[2][4];
            #pragma unroll
            for (int mf = 0; mf < 2; mf++) {
                int mo = warp_m*32 + mf*16;
                afr[mf][0] = A32[(mo + gq)     * 20 + kw + tg];
                afr[mf][1] = A32[(mo + gq + 8) * 20 + kw + tg];
                afr[mf][2] = A32[(mo + gq)     * 20 + kw + tg + 4];
                afr[mf][3] = A32[(mo + gq + 8) * 20 + kw + tg + 4];
            }
            uint32_t bfL[4][2], bfG[4][2];
            #pragma unroll
            for (int nf = 0; nf < 4; nf++) {
                int no = warp_n*32 + nf*8;
                bfL[nf][0] = BL[(no + gq) * 20 + kw + tg];
                bfL[nf][1] = BL[(no + gq) * 20 + kw + tg + 4];
                bfG[nf][0] = BG[(no + gq) * 20 + kw + tg];
                bfG[nf][1] = BG[(no + gq) * 20 + kw + tg + 4];
            }
            #pragma unroll
            for (int mf = 0; mf < 2; mf++)
                #pragma unroll
                for (int nf = 0; nf < 4; nf++) {
                    MMA16816(aL[mf][nf], afr[mf], bfL[nf]);
                    MMA16816(aG[mf][nf], afr[mf], bfG[nf]);
                }
        }
    }

    #pragma unroll
    for (int mf = 0; mf < 2; mf++) {
        #pragma unroll
        for (int nf = 0; nf < 4; nf++) {
            int rb = mtile*128 + warp_m*32 + mf*16 + gq;
            int cb = ntile*64 + warp_n*32 + nf*8 + tg*2;
            float2 bl2 = *reinterpret_cast<const float2*>(bl + cb);
            float2 bg2 = *reinterpret_cast<const float2*>(bg + cb);
            #pragma unroll
            for (int h = 0; h < 2; h++) {
                int r = rb + h*8;
                float2 u, g;
                u.x = aL[mf][nf][h*2 + 0] + bl2.x;
                u.y = aL[mf][nf][h*2 + 1] + bl2.y;
                g.x = aG[mf][nf][h*2 + 0] + bg2.x;
                g.y = aG[mf][nf][h*2 + 1] + bg2.y;
                *reinterpret_cast<float2*>(g_capU + (size_t)r * DD + cb) = u;
                *reinterpret_cast<float2*>(g_capG + (size_t)r * DD + cb) = g;
            }
        }
    }
}

// ---------------- main GEMM: 4-stage cp.async ring + ldmatrix + fused epilogue ----------------
#define ABUF (128*PITCH)            /* elems per A stage = 5120 */
#define BBUF (2*64*PITCH)           /* elems per B stage = 5120 */
#define BOFF (4*ABUF)               /* B region start    = 20480 */

__global__ __launch_bounds__(256)
void gemm_main(const float* __restrict__ cap) {
    extern __shared__ __nv_bfloat16 dsm[];
    int tid = threadIdx.x, lane = tid & 31, wid = tid >> 5;
    int warp_m = wid & 3, warp_n = wid >> 2;
    int gq = lane >> 2, tg = lane & 3;
    int ntile = blockIdx.x, mtile = blockIdx.y;

    float aL[2][4][4], aG[2][4][4];
    #pragma unroll
    for (int mf = 0; mf < 2; mf++)
        #pragma unroll
        for (int nf = 0; nf < 4; nf++)
            #pragma unroll
            for (int q = 0; q < 4; q++) { aL[mf][nf][q] = 0.f; aG[mf][nf][q] = 0.f; }

    int a_r0 = tid >> 2,         a_c0 = tid & 3;
    int a_r1 = (tid + 256) >> 2, a_c1 = tid & 3;
    int b_r  = tid >> 2,         b_c  = tid & 3;
    const __nv_bfloat16* Asrc0 = g_wcb + ((size_t)(mtile*128 + a_r0))*DD + a_c0*8;
    const __nv_bfloat16* Asrc1 = g_wcb + ((size_t)(mtile*128 + a_r1))*DD + a_c1*8;
    const __nv_bfloat16* BsrcL = g_WtL + ((size_t)(ntile*64 + b_r))*KK + DD + b_c*8;
    const __nv_bfloat16* BsrcG = g_WtG + ((size_t)(ntile*64 + b_r))*KK + DD + b_c*8;
    uint32_t Adst0[4], Adst1[4], BdstL[4], BdstG[4];
    #pragma unroll
    for (int b = 0; b < 4; b++) {
        Adst0[b] = smem_u32(dsm + b*ABUF + a_r0*PITCH + a_c0*8);
        Adst1[b] = smem_u32(dsm + b*ABUF + a_r1*PITCH + a_c1*8);
        BdstL[b] = smem_u32(dsm + BOFF + b*BBUF + b_r*PITCH + b_c*8);
        BdstG[b] = smem_u32(dsm + BOFF + b*BBUF + 64*PITCH + b_r*PITCH + b_c*8);
    }

    // ldmatrix per-thread source addresses (byte offsets within a stage buffer)
    // A x4: lanes 0-7 rows+0..7 k-lo | 8-15 rows+8..15 k-lo | 16-23 rows+0..7 k-hi | 24-31 rows+8..15 k-hi
    uint32_t aRowOff[2];
    #pragma unroll
    for (int mf = 0; mf < 2; mf++) {
        int row = warp_m*32 + mf*16 + (lane & 15);
        aRowOff[mf] = (uint32_t)(row*20 + (lane >> 4)*4) * 4;   // uint32 units -> bytes
    }
    // B x4 (two 8-n frags): lanes 0-7 n+0..7 k-lo | 8-15 n+0..7 k-hi | 16-23 n+8..15 k-lo | 24-31 n+8..15 k-hi
    uint32_t bRowOff[2];
    #pragma unroll
    for (int p = 0; p < 2; p++) {
        int row = warp_n*32 + p*16 + (lane & 7) + ((lane >> 4) << 3);
        bRowOff[p] = (uint32_t)(row*20 + ((lane >> 3) & 1)*4) * 4;
    }
    uint32_t Abyte[4], Bbyte[4];
    #pragma unroll
    for (int b = 0; b < 4; b++) {
        Abyte[b] = smem_u32(dsm + b*ABUF);
        Bbyte[b] = smem_u32(dsm + BOFF + b*BBUF);
    }
    const uint32_t BG_BYTES = 64*PITCH*2;   // 5120

    // prefetch 3 stages
    #pragma unroll
    for (int p = 0; p < 3; p++) {
        int k0 = p * 32;
        cpa16(Adst0[p], Asrc0 + k0); cpa16(Adst1[p], Asrc1 + k0);
        cpa16(BdstL[p], BsrcL + k0); cpa16(BdstG[p], BsrcG + k0);
        cpa_commit();
    }

    const int NSTEP = 32;
    for (int s = 0; s < NSTEP; s++) {
        cpa_wait2();
        __syncthreads();
        if (s + 3 < NSTEP) {
            int b = (s + 3) & 3;
            int k0 = (s + 3) * 32;
            cpa16(Adst0[b], Asrc0 + k0); cpa16(Adst1[b], Asrc1 + k0);
            cpa16(BdstL[b], BsrcL + k0); cpa16(BdstG[b], BsrcG + k0);
        }
        cpa_commit();   // always commit: keeps group counting uniform for wait_group 2
        int buf = s & 3;
        uint32_t ab = Abyte[buf], bb = Bbyte[buf];
        #pragma unroll
        for (int kk = 0; kk < 2; kk++) {
            uint32_t kwB = (uint32_t)(kk * 8) * 4;   // byte offset for k = kk*16
            uint32_t afr[2][4];
            #pragma unroll
            for (int mf = 0; mf < 2; mf++)
                LDSM4(afr[mf], ab + aRowOff[mf] + kwB);
            uint32_t bfL[2][4], bfG[2][4];
            #pragma unroll
            for (int p = 0; p < 2; p++) {
                LDSM4(bfL[p], bb + bRowOff[p] + kwB);
                LDSM4(bfG[p], bb + BG_BYTES + bRowOff[p] + kwB);
            }
            #pragma unroll
            for (int mf = 0; mf < 2; mf++)
                #pragma unroll
                for (int nf = 0; nf < 4; nf++) {
                    int p = nf >> 1, ix = (nf & 1) * 2;
                    MMA16816(aL[mf][nf], afr[mf], &bfL[p][ix]);
                    MMA16816(aG[mf][nf], afr[mf], &bfG[p][ix]);
                }
        }
    }

    // gated epilogue: q1 = cap*sig(g) + tanh(u)*(1-sig(g))
    #pragma unroll
    for (int mf = 0; mf < 2; mf++) {
        #pragma unroll
        for (int nf = 0; nf < 4; nf++) {
            int rb = mtile*128 + warp_m*32 + mf*16 + gq;
            int cb = ntile*64 + warp_n*32 + nf*8 + tg*2;
            #pragma unroll
            for (int h = 0; h < 2; h++) {
                int r = rb + h*8;
                int ccap = r / (II*TT), t = r % TT;
                size_t crow = ((size_t)(ccap*TT + t)) * DD + cb;
                float2 cp = *reinterpret_cast<const float2*>(cap + crow);
                float2 cu = *reinterpret_cast<const float2*>(g_capU + crow);
                float2 cg = *reinterpret_cast<const float2*>(g_capG + crow);
                float u0 = tanhf(aL[mf][nf][h*2 + 0] + cu.x);
                float u1 = tanhf(aL[mf][nf][h*2 + 1] + cu.y);
                float s0 = 1.f / (1.f + expf(-(aG[mf][nf][h*2 + 0] + cg.x)));
                float s1 = 1.f / (1.f + expf(-(aG[mf][nf][h*2 + 1] + cg.y)));
                float2 o;
                o.x = cp.x * s0 + u0 * (1.f - s0);
                o.y = cp.y * s1 + u1 * (1.f - s1);
                *reinterpret_cast<float2*>(g_q1 + (size_t)r * DD + cb) = o;
            }
        }
    }
}

// ---------------- launch ----------------
extern "C" void kernel_launch(void* const* d_in, const int* in_sizes, int n_in,
                              void* d_out, int out_size) {
    (void)in_sizes; (void)n_in; (void)out_size;
    const float* img    = (const float*)d_in[0];
    const float* cap    = (const float*)d_in[1];
    const float* W_lin  = (const float*)d_in[2];
    const float* b_lin  = (const float*)d_in[3];
    const float* W_gate = (const float*)d_in[4];
    const float* b_gate = (const float*)d_in[5];
    float* out = (float*)d_out;

    const int SMEM_ATTN = (RR*DD + RR*TT + TT*RR + 3*TT*16 + TT) * (int)sizeof(float);
    const int SMEM_GEMM = (BOFF + 4*BBUF) * (int)sizeof(__nv_bfloat16);   // 81920
    cudaFuncSetAttribute(attn_kernel, cudaFuncAttributeMaxDynamicSharedMemorySize, SMEM_ATTN);
    cudaFuncSetAttribute(gemm_main,   cudaFuncAttributeMaxDynamicSharedMemorySize, SMEM_GEMM);

    prep_wt<<<dim3(32, 64), dim3(32, 8)>>>(W_lin, 0);
    prep_wt<<<dim3(32, 64), dim3(32, 8)>>>(W_gate, 1);
    prep_capb<<<1280, 256>>>(cap);

    // caption-side half of the gated GEMM: image-independent, done once
    gemm_cap<<<dim3(16, 10), 256>>>(b_lin, b_gate);

    // iteration 0: attn + fused sim (writes score) + bf16 wc for GEMM
    attn_kernel<<<CC*II, 512, SMEM_ATTN>>>(img, cap, out, 0);

    // gated memory (only live once: iteration 1's update is dead code)
    gemm_main<<<dim3(16, 320), 256, SMEM_GEMM>>>(cap);

    // iteration 1: attn + fused sim (accumulates score)
    attn_kernel<<<CC*II, 512, SMEM_ATTN>>>(img, cap, out, 1);
}